// round 6
// baseline (speedup 1.0000x reference)
#include <cuda_runtime.h>
#include <math.h>

// ---------------------------------------------------------------------------
// VoxelBackBone8x decoder: 8 x (gather-GEMM over 27 taps + BN + relu)
// R5: f32x2 packed FMA + 8x8 register blocking + materialized activations
//     + per-warp (32-row) tap skip. Heavy layers use gemm2<> (dynamic smem),
//     16-ch tail layers keep the old kernel.
// ---------------------------------------------------------------------------

#define MAXROWS 102400

__device__ float g_bufA[MAXROWS * 64];
__device__ float g_bufB[MAXROWS * 64];
__device__ float g_stats[8 * 2 * 64];   // per layer: [sum(64), sumsq(64)]

__global__ void zero_stats_kernel() {
    int t = blockIdx.x * blockDim.x + threadIdx.x;
    if (t < 8 * 2 * 64) g_stats[t] = 0.f;
}

// ---------------------------------------------------------------------------
// f32x2 helpers
// ---------------------------------------------------------------------------
__device__ __forceinline__ void ffma2(unsigned long long& d, unsigned long long a,
                                      unsigned long long b) {
    asm("fma.rn.f32x2 %0, %1, %2, %0;" : "+l"(d) : "l"(a), "l"(b));
}
__device__ __forceinline__ unsigned long long packf2(float x) {
    unsigned long long r;
    unsigned int u = __float_as_uint(x);
    asm("mov.b64 %0, {%1, %1};" : "=l"(r) : "r"(u));
    return r;
}
__device__ __forceinline__ float2 unpackf2(unsigned long long v) {
    float2 f;
    asm("mov.b64 {%0, %1}, %2;" : "=f"(f.x), "=f"(f.y) : "l"(v));
    return f;
}

// ---------------------------------------------------------------------------
// In-place BN + relu: y = relu(y*a + b), affine computed from stats in-block.
// ---------------------------------------------------------------------------
__global__ void act_kernel(float* __restrict__ y, const float* __restrict__ stats,
                           const float* __restrict__ g, const float* __restrict__ b,
                           int N, int CO) {
    __shared__ float sa[64], sb[64];
    int c = threadIdx.x;
    if (c < CO) {
        float invN = 1.0f / (float)N;
        float mu = stats[c] * invN;
        float var = stats[64 + c] * invN - mu * mu;
        float a = g[c] * rsqrtf(var + 1e-3f);
        sa[c] = a;
        sb[c] = b[c] - mu * a;
    }
    __syncthreads();
    int total4 = N * CO / 4;
    int co4 = CO / 4;
    for (int i = blockIdx.x * blockDim.x + threadIdx.x; i < total4;
         i += gridDim.x * blockDim.x) {
        float4 v = ((float4*)y)[i];
        int cc = (i % co4) * 4;
        v.x = fmaxf(fmaf(v.x, sa[cc + 0], sb[cc + 0]), 0.f);
        v.y = fmaxf(fmaf(v.y, sa[cc + 1], sb[cc + 1]), 0.f);
        v.z = fmaxf(fmaf(v.z, sa[cc + 2], sb[cc + 2]), 0.f);
        v.w = fmaxf(fmaf(v.w, sa[cc + 3], sb[cc + 3]), 0.f);
        ((float4*)y)[i] = v;
    }
}

// final layer: out[n,3] = y[n,3]*a + b (no relu), affine from stats
__global__ void out_kernel(const float* __restrict__ y, const float* __restrict__ stats,
                           const float* __restrict__ g, const float* __restrict__ b,
                           float* __restrict__ out, int N) {
    __shared__ float sa[3], sb[3];
    int c = threadIdx.x;
    if (c < 3) {
        float invN = 1.0f / (float)N;
        float mu = stats[c] * invN;
        float var = stats[64 + c] * invN - mu * mu;
        float a = g[c] * rsqrtf(var + 1e-3f);
        sa[c] = a;
        sb[c] = b[c] - mu * a;
    }
    __syncthreads();
    int total = N * 3;
    for (int i = blockIdx.x * blockDim.x + threadIdx.x; i < total;
         i += gridDim.x * blockDim.x) {
        int j = i % 3;
        out[i] = fmaf(y[i], sa[j], sb[j]);
    }
}

// ---------------------------------------------------------------------------
// gemm2: heavy-layer gather-GEMM. 256 threads.
//   G = CO/8 column groups (8 cols/thread, held as 4 f32x2 accum pairs)
//   ROWG = 256/G row groups, RPT rows each -> TN = ROWG*RPT rows per tile
//   SUB = 32*RPT/G rows per warp (= 32 for all instantiations here)
//   per-warp tap skip via s_live[subset][tap]; block-level skip via s_flag.
//   Inputs pre-activated; writes raw y + per-channel sum/sumsq stats.
// ---------------------------------------------------------------------------
template <int CI, int CO, int RPT>
__launch_bounds__(256, 2)
__global__ void gemm2_kernel(const float* __restrict__ in,
                             const int* __restrict__ nbr,
                             const float* __restrict__ W,   // [27][CI][CO]
                             float* __restrict__ out,       // [N][CO] raw
                             float* __restrict__ stats,     // [sum(64), sumsq(64)]
                             int N) {
    constexpr int G = CO / 8;
    constexpr int ROWG = 256 / G;
    constexpr int TN = ROWG * RPT;
    constexpr int CIP = CI + 4;
    constexpr int SUB = 32 * RPT / G;    // rows covered by one warp
    constexpr int NSUB = TN / SUB;       // == 8
    constexpr int C4 = CI / 4;

    extern __shared__ float smem[];
    float* s_x = smem;                   // TN * CIP
    float* s_w = smem + TN * CIP;        // CI * CO

    __shared__ int s_live[NSUB][27];
    __shared__ int s_flag[27];
    __shared__ float s_stats[2][CO];

    const int tid = threadIdx.x;
    const int rowbase = blockIdx.x * TN;

    for (int i = tid; i < NSUB * 27; i += 256) ((int*)s_live)[i] = 0;
    if (tid < CO) { s_stats[0][tid] = 0.f; s_stats[1][tid] = 0.f; }
    __syncthreads();

    // liveness pre-pass
    for (int i = tid; i < TN * 27; i += 256) {
        int r = i / 27;
        int k = i - r * 27;
        int gr = rowbase + r;
        if (gr < N && nbr[(size_t)gr * 27 + k] >= 0) s_live[r / SUB][k] = 1;
    }
    __syncthreads();
    if (tid < 27) {
        int f = 0;
#pragma unroll
        for (int s = 0; s < NSUB; ++s) f |= s_live[s][tid];
        s_flag[tid] = f;
    }
    __syncthreads();

    const int cg = tid % G;
    const int rg = tid / G;
    const int r0 = rg * RPT;
    const int mysub = r0 / SUB;          // uniform within warp

    unsigned long long acc[RPT][4];
#pragma unroll
    for (int i = 0; i < RPT; ++i)
#pragma unroll
        for (int j = 0; j < 4; ++j) acc[i][j] = 0ULL;

    for (int k = 0; k < 27; ++k) {
        if (!s_flag[k]) continue;
        __syncthreads();   // previous tap's readers done

        // stage W[k]
        {
            const float4* Wk = (const float4*)(W + (size_t)k * CI * CO);
            for (int v = tid; v < CI * CO / 4; v += 256) ((float4*)s_w)[v] = Wk[v];
        }
        // gather features for this tap (skip dead 32-row subsets)
        for (int v = tid; v < TN * C4; v += 256) {
            int r = v / C4;
            int c4 = v - r * C4;
            if (!s_live[r / SUB][k]) continue;
            int gr = rowbase + r;
            int idx = (gr < N) ? nbr[(size_t)gr * 27 + k] : -1;
            float4 val = make_float4(0.f, 0.f, 0.f, 0.f);
            if (idx >= 0) val = *(const float4*)(in + (size_t)idx * CI + c4 * 4);
            *(float4*)(s_x + r * CIP + c4 * 4) = val;
        }
        __syncthreads();

        if (!s_live[mysub][k]) continue;  // per-warp skip (no syncs below)

#pragma unroll 2
        for (int c = 0; c < CI; c += 2) {
            ulonglong2 wa0 = *(const ulonglong2*)(s_w + (c + 0) * CO + 8 * cg);
            ulonglong2 wa1 = *(const ulonglong2*)(s_w + (c + 0) * CO + 8 * cg + 4);
            ulonglong2 wb0 = *(const ulonglong2*)(s_w + (c + 1) * CO + 8 * cg);
            ulonglong2 wb1 = *(const ulonglong2*)(s_w + (c + 1) * CO + 8 * cg + 4);
#pragma unroll
            for (int i = 0; i < RPT; ++i) {
                float2 xv = *(const float2*)(s_x + (r0 + i) * CIP + c);
                unsigned long long xa = packf2(xv.x);
                unsigned long long xb = packf2(xv.y);
                ffma2(acc[i][0], xa, wa0.x);
                ffma2(acc[i][1], xa, wa0.y);
                ffma2(acc[i][2], xa, wa1.x);
                ffma2(acc[i][3], xa, wa1.y);
                ffma2(acc[i][0], xb, wb0.x);
                ffma2(acc[i][1], xb, wb0.y);
                ffma2(acc[i][2], xb, wb1.x);
                ffma2(acc[i][3], xb, wb1.y);
            }
        }
    }

    // epilogue: store raw y + accumulate stats
#pragma unroll
    for (int j = 0; j < 4; ++j) {
        float s1 = 0.f, s2 = 0.f, t1 = 0.f, t2 = 0.f;
#pragma unroll
        for (int i = 0; i < RPT; ++i) {
            int gr = rowbase + r0 + i;
            if (gr < N) {
                float2 p = unpackf2(acc[i][j]);
                s1 += p.x; s2 += p.x * p.x;
                t1 += p.y; t2 += p.y * p.y;
            }
        }
        atomicAdd(&s_stats[0][8 * cg + 2 * j + 0], s1);
        atomicAdd(&s_stats[1][8 * cg + 2 * j + 0], s2);
        atomicAdd(&s_stats[0][8 * cg + 2 * j + 1], t1);
        atomicAdd(&s_stats[1][8 * cg + 2 * j + 1], t2);
    }
#pragma unroll
    for (int i = 0; i < RPT; ++i) {
        int gr = rowbase + r0 + i;
        if (gr < N) {
            float2 p0 = unpackf2(acc[i][0]);
            float2 p1 = unpackf2(acc[i][1]);
            float2 p2 = unpackf2(acc[i][2]);
            float2 p3 = unpackf2(acc[i][3]);
            *(float4*)(out + (size_t)gr * CO + 8 * cg) =
                make_float4(p0.x, p0.y, p1.x, p1.y);
            *(float4*)(out + (size_t)gr * CO + 8 * cg + 4) =
                make_float4(p2.x, p2.y, p3.x, p3.y);
        }
    }
    __syncthreads();
    if (tid < CO) {
        atomicAdd(&stats[tid], s_stats[0][tid]);
        atomicAdd(&stats[64 + tid], s_stats[1][tid]);
    }
}

// ---------------------------------------------------------------------------
// Old-style kernel for the cheap 16-channel tail layers (APPLY=false: inputs
// are pre-activated). Unchanged from R4 otherwise.
// ---------------------------------------------------------------------------
template <int CI, int CO, int COP, int TN, int G, int RPT, bool APPLY>
__launch_bounds__(256, 2)
__global__ void gemm_gather_kernel(const float* __restrict__ in,
                                   const int* __restrict__ nbr,
                                   const float* __restrict__ W,
                                   const float* __restrict__ aff,
                                   float* __restrict__ out,
                                   float* __restrict__ stats,
                                   int N) {
    constexpr int CIP = CI + 4;

    __shared__ float s_x[TN * CIP];
    __shared__ float s_w[CI * COP];
    __shared__ int   s_nbr[TN * 27];
    __shared__ int   s_flag[27];
    __shared__ float s_stats[2][COP];

    const int tid = threadIdx.x;
    const int rowbase = blockIdx.x * TN;

    if (tid < 27) s_flag[tid] = 0;
    if (tid < COP) { s_stats[0][tid] = 0.f; s_stats[1][tid] = 0.f; }
    __syncthreads();

    for (int i = tid; i < TN * 27; i += 256) {
        int r = i / 27;
        int k = i - r * 27;
        int gr = rowbase + r;
        int v = (gr < N) ? nbr[gr * 27 + k] : -1;
        s_nbr[i] = v;
        if (v >= 0) s_flag[k] = 1;
    }
    __syncthreads();

    const int cg = tid % G;
    const int rg = tid / G;
    const int r0 = rg * RPT;

    float acc[RPT][4];
#pragma unroll
    for (int i = 0; i < RPT; ++i)
#pragma unroll
        for (int j = 0; j < 4; ++j) acc[i][j] = 0.f;

    for (int k = 0; k < 27; ++k) {
        if (!s_flag[k]) continue;
        __syncthreads();

        if (CO == COP) {
            const float4* Wk = (const float4*)(W + (size_t)k * CI * CO);
            for (int v = tid; v < CI * CO / 4; v += 256)
                ((float4*)s_w)[v] = Wk[v];
        } else {
            const float* Wk = W + (size_t)k * CI * CO;
            for (int v = tid; v < CI * COP; v += 256) {
                int c = v / COP, j = v - c * COP;
                s_w[v] = (j < CO) ? Wk[c * CO + j] : 0.f;
            }
        }

        for (int v = tid; v < TN * CI / 4; v += 256) {
            int r = v / (CI / 4);
            int c4 = v - r * (CI / 4);
            int idx = s_nbr[r * 27 + k];
            float4 val = make_float4(0.f, 0.f, 0.f, 0.f);
            if (idx >= 0)
                val = *(const float4*)(in + (size_t)idx * CI + c4 * 4);
            *(float4*)(s_x + r * CIP + c4 * 4) = val;
        }
        __syncthreads();

#pragma unroll
        for (int c = 0; c < CI; c += 4) {
            float4 w0 = *(const float4*)(s_w + (c + 0) * COP + 4 * cg);
            float4 w1 = *(const float4*)(s_w + (c + 1) * COP + 4 * cg);
            float4 w2 = *(const float4*)(s_w + (c + 2) * COP + 4 * cg);
            float4 w3 = *(const float4*)(s_w + (c + 3) * COP + 4 * cg);
#pragma unroll
            for (int i = 0; i < RPT; ++i) {
                float4 xv = *(const float4*)(s_x + (r0 + i) * CIP + c);
                acc[i][0] = fmaf(xv.x, w0.x, acc[i][0]);
                acc[i][1] = fmaf(xv.x, w0.y, acc[i][1]);
                acc[i][2] = fmaf(xv.x, w0.z, acc[i][2]);
                acc[i][3] = fmaf(xv.x, w0.w, acc[i][3]);
                acc[i][0] = fmaf(xv.y, w1.x, acc[i][0]);
                acc[i][1] = fmaf(xv.y, w1.y, acc[i][1]);
                acc[i][2] = fmaf(xv.y, w1.z, acc[i][2]);
                acc[i][3] = fmaf(xv.y, w1.w, acc[i][3]);
                acc[i][0] = fmaf(xv.z, w2.x, acc[i][0]);
                acc[i][1] = fmaf(xv.z, w2.y, acc[i][1]);
                acc[i][2] = fmaf(xv.z, w2.z, acc[i][2]);
                acc[i][3] = fmaf(xv.z, w2.w, acc[i][3]);
                acc[i][0] = fmaf(xv.w, w3.x, acc[i][0]);
                acc[i][1] = fmaf(xv.w, w3.y, acc[i][1]);
                acc[i][2] = fmaf(xv.w, w3.z, acc[i][2]);
                acc[i][3] = fmaf(xv.w, w3.w, acc[i][3]);
            }
        }
    }

#pragma unroll
    for (int j = 0; j < 4; ++j) {
        float s1 = 0.f, s2 = 0.f;
#pragma unroll
        for (int i = 0; i < RPT; ++i) {
            int gr = rowbase + r0 + i;
            if (gr < N) {
                float y = acc[i][j];
                s1 += y;
                s2 += y * y;
            }
        }
        atomicAdd(&s_stats[0][4 * cg + j], s1);
        atomicAdd(&s_stats[1][4 * cg + j], s2);
    }
#pragma unroll
    for (int i = 0; i < RPT; ++i) {
        int gr = rowbase + r0 + i;
        if (gr < N) {
            if (CO == COP) {
                *(float4*)(out + (size_t)gr * CO + 4 * cg) =
                    make_float4(acc[i][0], acc[i][1], acc[i][2], acc[i][3]);
            } else {
#pragma unroll
                for (int j = 0; j < CO; ++j)
                    out[(size_t)gr * CO + j] = acc[i][j];
            }
        }
    }
    __syncthreads();
    if (tid < CO) {
        atomicAdd(&stats[tid], s_stats[0][tid]);
        atomicAdd(&stats[64 + tid], s_stats[1][tid]);
    }
}

extern "C" void kernel_launch(void* const* d_in, const int* in_sizes, int n_in,
                              void* d_out, int out_size) {
    const int* nbr4  = (const int*)d_in[0];
    const int* inv43 = (const int*)d_in[1];
    const int* nbr3  = (const int*)d_in[2];
    const int* inv32 = (const int*)d_in[3];
    const int* nbr2  = (const int*)d_in[4];
    const int* inv21 = (const int*)d_in[5];
    const int* nbr1  = (const int*)d_in[6];
    const float* x   = (const float*)d_in[7];

    const float* W_m4 = (const float*)d_in[8];
    const float* g_m4 = (const float*)d_in[9];
    const float* b_m4 = (const float*)d_in[10];
    const float* W_i4 = (const float*)d_in[11];
    const float* g_i4 = (const float*)d_in[12];
    const float* b_i4 = (const float*)d_in[13];
    const float* W_m3 = (const float*)d_in[14];
    const float* g_m3 = (const float*)d_in[15];
    const float* b_m3 = (const float*)d_in[16];
    const float* W_i3 = (const float*)d_in[17];
    const float* g_i3 = (const float*)d_in[18];
    const float* b_i3 = (const float*)d_in[19];
    const float* W_m2 = (const float*)d_in[20];
    const float* g_m2 = (const float*)d_in[21];
    const float* b_m2 = (const float*)d_in[22];
    const float* W_i2 = (const float*)d_in[23];
    const float* g_i2 = (const float*)d_in[24];
    const float* b_i2 = (const float*)d_in[25];
    const float* W_m1 = (const float*)d_in[26];
    const float* g_m1 = (const float*)d_in[27];
    const float* b_m1 = (const float*)d_in[28];
    const float* W_c5 = (const float*)d_in[29];
    const float* g_c5 = (const float*)d_in[30];
    const float* b_c5 = (const float*)d_in[31];

    const int n4 = in_sizes[0] / 27;
    const int n3 = in_sizes[1] / 27;
    const int n2 = in_sizes[3] / 27;
    const int n1 = in_sizes[5] / 27;

    float *bufA, *bufB, *stats;
    cudaGetSymbolAddress((void**)&bufA, g_bufA);
    cudaGetSymbolAddress((void**)&bufB, g_bufB);
    cudaGetSymbolAddress((void**)&stats, g_stats);

    // dynamic smem opt-in for the big instantiations (idempotent, every call)
    constexpr int SM_6464 = (256 * 68 + 64 * 64) * 4;   // 86016
    constexpr int SM_6432 = (256 * 68 + 64 * 32) * 4;   // 77824
    constexpr int SM_3232 = (256 * 36 + 32 * 32) * 4;   // 40960
    cudaFuncSetAttribute(gemm2_kernel<64, 64, 8>,
                         cudaFuncAttributeMaxDynamicSharedMemorySize, SM_6464);
    cudaFuncSetAttribute(gemm2_kernel<64, 32, 4>,
                         cudaFuncAttributeMaxDynamicSharedMemorySize, SM_6432);

    zero_stats_kernel<<<4, 256>>>();

    // L1: m4 (x -> A), 64->64, N=n4
    gemm2_kernel<64, 64, 8><<<(n4 + 255) / 256, 256, SM_6464>>>(
        x, nbr4, W_m4, bufA, stats + 0 * 128, n4);
    act_kernel<<<512, 256>>>(bufA, stats + 0 * 128, g_m4, b_m4, n4, 64);

    // L2: i4 (A -> B), 64->64, N=n3
    gemm2_kernel<64, 64, 8><<<(n3 + 255) / 256, 256, SM_6464>>>(
        bufA, inv43, W_i4, bufB, stats + 1 * 128, n3);
    act_kernel<<<512, 256>>>(bufB, stats + 1 * 128, g_i4, b_i4, n3, 64);

    // L3: m3 (B -> A), 64->64, N=n3
    gemm2_kernel<64, 64, 8><<<(n3 + 255) / 256, 256, SM_6464>>>(
        bufB, nbr3, W_m3, bufA, stats + 2 * 128, n3);
    act_kernel<<<512, 256>>>(bufA, stats + 2 * 128, g_m3, b_m3, n3, 64);

    // L4: i3 (A -> B), 64->32, N=n2
    gemm2_kernel<64, 32, 4><<<(n2 + 255) / 256, 256, SM_6432>>>(
        bufA, inv32, W_i3, bufB, stats + 3 * 128, n2);
    act_kernel<<<512, 256>>>(bufB, stats + 3 * 128, g_i3, b_i3, n2, 32);

    // L5: m2 (B -> A), 32->32, N=n2
    gemm2_kernel<32, 32, 4><<<(n2 + 255) / 256, 256, SM_3232>>>(
        bufB, nbr2, W_m2, bufA, stats + 4 * 128, n2);
    act_kernel<<<512, 256>>>(bufA, stats + 4 * 128, g_m2, b_m2, n2, 32);

    // L6: i2 (A -> B), 32->16, N=n1
    gemm_gather_kernel<32, 16, 16, 64, 4, 1, false>
        <<<(n1 + 63) / 64, 256>>>(bufA, inv21, W_i2, nullptr, bufB,
                                  stats + 5 * 128, n1);
    act_kernel<<<512, 256>>>(bufB, stats + 5 * 128, g_i2, b_i2, n1, 16);

    // L7: m1 (B -> A), 16->16, N=n1
    gemm_gather_kernel<16, 16, 16, 64, 4, 1, false>
        <<<(n1 + 63) / 64, 256>>>(bufB, nbr1, W_m1, nullptr, bufA,
                                  stats + 6 * 128, n1);
    act_kernel<<<512, 256>>>(bufA, stats + 6 * 128, g_m1, b_m1, n1, 16);

    // L8: c5 (A -> B raw), 16->3
    gemm_gather_kernel<16, 3, 4, 256, 1, 1, false>
        <<<(n1 + 255) / 256, 256>>>(bufA, nbr1, W_c5, nullptr, bufB,
                                    stats + 7 * 128, n1);

    // final normalize (no relu)
    out_kernel<<<256, 256>>>(bufB, stats + 7 * 128, g_c5, b_c5,
                             (float*)d_out, n1);
}

// round 7
// speedup vs baseline: 1.0500x; 1.0500x over previous
#include <cuda_runtime.h>
#include <math.h>

// ---------------------------------------------------------------------------
// VoxelBackBone8x decoder: 8 x (gather-GEMM over 27 taps + BN + relu)
// R6: f32x2 FFMA2 with 4-row x 8-col per-thread tiles, TN=128/256 tiles sized
//     for >=2 CTAs/SM (R5's 256-row tile collapsed occupancy). Per-warp tap
//     skip. BN via stats + separate act kernel (materialized activations).
// ---------------------------------------------------------------------------

#define MAXROWS 102400

__device__ float g_bufA[MAXROWS * 64];
__device__ float g_bufB[MAXROWS * 64];
__device__ float g_stats[8 * 2 * 64];   // per layer: [sum(64), sumsq(64)]

__global__ void zero_stats_kernel() {
    int t = blockIdx.x * blockDim.x + threadIdx.x;
    if (t < 8 * 2 * 64) g_stats[t] = 0.f;
}

// ---------------------------------------------------------------------------
// f32x2 helpers
// ---------------------------------------------------------------------------
__device__ __forceinline__ void ffma2(unsigned long long& d, unsigned long long a,
                                      unsigned long long b) {
    asm("fma.rn.f32x2 %0, %1, %2, %0;" : "+l"(d) : "l"(a), "l"(b));
}
__device__ __forceinline__ unsigned long long packf2(float x) {
    unsigned long long r;
    unsigned int u = __float_as_uint(x);
    asm("mov.b64 %0, {%1, %1};" : "=l"(r) : "r"(u));
    return r;
}
__device__ __forceinline__ float2 unpackf2(unsigned long long v) {
    float2 f;
    asm("mov.b64 {%0, %1}, %2;" : "=f"(f.x), "=f"(f.y) : "l"(v));
    return f;
}

// ---------------------------------------------------------------------------
// In-place BN + relu: y = relu(y*a + b), affine computed from stats in-block.
// ---------------------------------------------------------------------------
__global__ void act_kernel(float* __restrict__ y, const float* __restrict__ stats,
                           const float* __restrict__ g, const float* __restrict__ b,
                           int N, int CO) {
    __shared__ float sa[64], sb[64];
    int c = threadIdx.x;
    if (c < CO) {
        float invN = 1.0f / (float)N;
        float mu = stats[c] * invN;
        float var = stats[64 + c] * invN - mu * mu;
        float a = g[c] * rsqrtf(var + 1e-3f);
        sa[c] = a;
        sb[c] = b[c] - mu * a;
    }
    __syncthreads();
    int total4 = N * CO / 4;
    int co4 = CO / 4;
    for (int i = blockIdx.x * blockDim.x + threadIdx.x; i < total4;
         i += gridDim.x * blockDim.x) {
        float4 v = ((float4*)y)[i];
        int cc = (i % co4) * 4;
        v.x = fmaxf(fmaf(v.x, sa[cc + 0], sb[cc + 0]), 0.f);
        v.y = fmaxf(fmaf(v.y, sa[cc + 1], sb[cc + 1]), 0.f);
        v.z = fmaxf(fmaf(v.z, sa[cc + 2], sb[cc + 2]), 0.f);
        v.w = fmaxf(fmaf(v.w, sa[cc + 3], sb[cc + 3]), 0.f);
        ((float4*)y)[i] = v;
    }
}

// final layer: out[n,3] = y[n,3]*a + b (no relu), affine from stats
__global__ void out_kernel(const float* __restrict__ y, const float* __restrict__ stats,
                           const float* __restrict__ g, const float* __restrict__ b,
                           float* __restrict__ out, int N) {
    __shared__ float sa[3], sb[3];
    int c = threadIdx.x;
    if (c < 3) {
        float invN = 1.0f / (float)N;
        float mu = stats[c] * invN;
        float var = stats[64 + c] * invN - mu * mu;
        float a = g[c] * rsqrtf(var + 1e-3f);
        sa[c] = a;
        sb[c] = b[c] - mu * a;
    }
    __syncthreads();
    int total = N * 3;
    for (int i = blockIdx.x * blockDim.x + threadIdx.x; i < total;
         i += gridDim.x * blockDim.x) {
        int j = i % 3;
        out[i] = fmaf(y[i], sa[j], sb[j]);
    }
}

// ---------------------------------------------------------------------------
// gemm2: gather-GEMM, NT threads, per-thread tile = RPT rows x 8 cols (f32x2).
//   G = CO/8 column groups; ROWG = NT/G row groups; TN = ROWG*RPT rows/tile.
//   SUB = (32/G)*RPT rows covered per warp -> per-warp tap skip.
//   Inputs pre-activated; writes raw y + per-channel sum/sumsq stats.
// ---------------------------------------------------------------------------
template <int CI, int CO, int NT, int RPT, int MB>
__launch_bounds__(NT, MB)
__global__ void gemm2_kernel(const float* __restrict__ in,
                             const int* __restrict__ nbr,
                             const float* __restrict__ W,   // [27][CI][CO]
                             float* __restrict__ out,       // [N][CO] raw
                             float* __restrict__ stats,     // [sum(64), sumsq(64)]
                             int N) {
    constexpr int G = CO / 8;
    constexpr int ROWG = NT / G;
    constexpr int TN = ROWG * RPT;
    constexpr int CIP = CI + 4;
    constexpr int SUB = (32 / G) * RPT;  // rows covered by one warp
    constexpr int NSUB = TN / SUB;
    constexpr int C4 = CI / 4;

    extern __shared__ float smem[];
    float* s_x = smem;                   // TN * CIP
    float* s_w = smem + TN * CIP;        // CI * CO

    __shared__ int s_live[NSUB][27];
    __shared__ int s_flag[27];
    __shared__ float s_stats[2][CO];

    const int tid = threadIdx.x;
    const int rowbase = blockIdx.x * TN;

    for (int i = tid; i < NSUB * 27; i += NT) ((int*)s_live)[i] = 0;
    if (tid < CO) { s_stats[0][tid] = 0.f; s_stats[1][tid] = 0.f; }
    __syncthreads();

    // liveness pre-pass
    for (int i = tid; i < TN * 27; i += NT) {
        int r = i / 27;
        int k = i - r * 27;
        int gr = rowbase + r;
        if (gr < N && nbr[(size_t)gr * 27 + k] >= 0) s_live[r / SUB][k] = 1;
    }
    __syncthreads();
    if (tid < 27) {
        int f = 0;
#pragma unroll
        for (int s = 0; s < NSUB; ++s) f |= s_live[s][tid];
        s_flag[tid] = f;
    }
    __syncthreads();

    const int cg = tid % G;
    const int rg = tid / G;
    const int r0 = rg * RPT;
    const int mysub = r0 / SUB;          // uniform within warp

    unsigned long long acc[RPT][4];
#pragma unroll
    for (int i = 0; i < RPT; ++i)
#pragma unroll
        for (int j = 0; j < 4; ++j) acc[i][j] = 0ULL;

    for (int k = 0; k < 27; ++k) {
        if (!s_flag[k]) continue;
        __syncthreads();   // previous tap's readers done

        // stage W[k]
        {
            const float4* Wk = (const float4*)(W + (size_t)k * CI * CO);
            for (int v = tid; v < CI * CO / 4; v += NT) ((float4*)s_w)[v] = Wk[v];
        }
        // gather features for this tap (skip dead SUB-row subsets)
        for (int v = tid; v < TN * C4; v += NT) {
            int r = v / C4;
            int c4 = v - r * C4;
            if (!s_live[r / SUB][k]) continue;
            int gr = rowbase + r;
            int idx = (gr < N) ? nbr[(size_t)gr * 27 + k] : -1;
            float4 val = make_float4(0.f, 0.f, 0.f, 0.f);
            if (idx >= 0) val = *(const float4*)(in + (size_t)idx * CI + c4 * 4);
            *(float4*)(s_x + r * CIP + c4 * 4) = val;
        }
        __syncthreads();

        if (!s_live[mysub][k]) continue;  // per-warp skip (no syncs below)

#pragma unroll 2
        for (int c = 0; c < CI; c += 2) {
            ulonglong2 wa0 = *(const ulonglong2*)(s_w + (c + 0) * CO + 8 * cg);
            ulonglong2 wa1 = *(const ulonglong2*)(s_w + (c + 0) * CO + 8 * cg + 4);
            ulonglong2 wb0 = *(const ulonglong2*)(s_w + (c + 1) * CO + 8 * cg);
            ulonglong2 wb1 = *(const ulonglong2*)(s_w + (c + 1) * CO + 8 * cg + 4);
#pragma unroll
            for (int i = 0; i < RPT; ++i) {
                float2 xv = *(const float2*)(s_x + (r0 + i) * CIP + c);
                unsigned long long xa = packf2(xv.x);
                unsigned long long xb = packf2(xv.y);
                ffma2(acc[i][0], xa, wa0.x);
                ffma2(acc[i][1], xa, wa0.y);
                ffma2(acc[i][2], xa, wa1.x);
                ffma2(acc[i][3], xa, wa1.y);
                ffma2(acc[i][0], xb, wb0.x);
                ffma2(acc[i][1], xb, wb0.y);
                ffma2(acc[i][2], xb, wb1.x);
                ffma2(acc[i][3], xb, wb1.y);
            }
        }
    }

    // epilogue: store raw y + accumulate stats
#pragma unroll
    for (int j = 0; j < 4; ++j) {
        float s1 = 0.f, s2 = 0.f, t1 = 0.f, t2 = 0.f;
#pragma unroll
        for (int i = 0; i < RPT; ++i) {
            int gr = rowbase + r0 + i;
            if (gr < N) {
                float2 p = unpackf2(acc[i][j]);
                s1 += p.x; s2 += p.x * p.x;
                t1 += p.y; t2 += p.y * p.y;
            }
        }
        atomicAdd(&s_stats[0][8 * cg + 2 * j + 0], s1);
        atomicAdd(&s_stats[1][8 * cg + 2 * j + 0], s2);
        atomicAdd(&s_stats[0][8 * cg + 2 * j + 1], t1);
        atomicAdd(&s_stats[1][8 * cg + 2 * j + 1], t2);
    }
#pragma unroll
    for (int i = 0; i < RPT; ++i) {
        int gr = rowbase + r0 + i;
        if (gr < N) {
            float2 p0 = unpackf2(acc[i][0]);
            float2 p1 = unpackf2(acc[i][1]);
            float2 p2 = unpackf2(acc[i][2]);
            float2 p3 = unpackf2(acc[i][3]);
            *(float4*)(out + (size_t)gr * CO + 8 * cg) =
                make_float4(p0.x, p0.y, p1.x, p1.y);
            *(float4*)(out + (size_t)gr * CO + 8 * cg + 4) =
                make_float4(p2.x, p2.y, p3.x, p3.y);
        }
    }
    __syncthreads();
    if (tid < CO) {
        atomicAdd(&stats[tid], s_stats[0][tid]);
        atomicAdd(&stats[64 + tid], s_stats[1][tid]);
    }
}

// ---------------------------------------------------------------------------
// Old-style scalar kernel, kept only for the tiny 16->3 final conv.
// ---------------------------------------------------------------------------
template <int CI, int CO, int COP, int TN, int G, int RPT>
__launch_bounds__(256, 2)
__global__ void gemm_gather_kernel(const float* __restrict__ in,
                                   const int* __restrict__ nbr,
                                   const float* __restrict__ W,
                                   float* __restrict__ out,
                                   float* __restrict__ stats,
                                   int N) {
    constexpr int CIP = CI + 4;

    __shared__ float s_x[TN * CIP];
    __shared__ float s_w[CI * COP];
    __shared__ int   s_nbr[TN * 27];
    __shared__ int   s_flag[27];
    __shared__ float s_stats[2][COP];

    const int tid = threadIdx.x;
    const int rowbase = blockIdx.x * TN;

    if (tid < 27) s_flag[tid] = 0;
    if (tid < COP) { s_stats[0][tid] = 0.f; s_stats[1][tid] = 0.f; }
    __syncthreads();

    for (int i = tid; i < TN * 27; i += 256) {
        int r = i / 27;
        int k = i - r * 27;
        int gr = rowbase + r;
        int v = (gr < N) ? nbr[gr * 27 + k] : -1;
        s_nbr[i] = v;
        if (v >= 0) s_flag[k] = 1;
    }
    __syncthreads();

    const int cg = tid % G;
    const int rg = tid / G;
    const int r0 = rg * RPT;

    float acc[RPT][4];
#pragma unroll
    for (int i = 0; i < RPT; ++i)
#pragma unroll
        for (int j = 0; j < 4; ++j) acc[i][j] = 0.f;

    for (int k = 0; k < 27; ++k) {
        if (!s_flag[k]) continue;
        __syncthreads();

        {
            const float* Wk = W + (size_t)k * CI * CO;
            for (int v = tid; v < CI * COP; v += 256) {
                int c = v / COP, j = v - c * COP;
                s_w[v] = (j < CO) ? Wk[c * CO + j] : 0.f;
            }
        }

        for (int v = tid; v < TN * CI / 4; v += 256) {
            int r = v / (CI / 4);
            int c4 = v - r * (CI / 4);
            int idx = s_nbr[r * 27 + k];
            float4 val = make_float4(0.f, 0.f, 0.f, 0.f);
            if (idx >= 0)
                val = *(const float4*)(in + (size_t)idx * CI + c4 * 4);
            *(float4*)(s_x + r * CIP + c4 * 4) = val;
        }
        __syncthreads();

#pragma unroll
        for (int c = 0; c < CI; c += 4) {
            float4 w0 = *(const float4*)(s_w + (c + 0) * COP + 4 * cg);
            float4 w1 = *(const float4*)(s_w + (c + 1) * COP + 4 * cg);
            float4 w2 = *(const float4*)(s_w + (c + 2) * COP + 4 * cg);
            float4 w3 = *(const float4*)(s_w + (c + 3) * COP + 4 * cg);
#pragma unroll
            for (int i = 0; i < RPT; ++i) {
                float4 xv = *(const float4*)(s_x + (r0 + i) * CIP + c);
                acc[i][0] = fmaf(xv.x, w0.x, acc[i][0]);
                acc[i][1] = fmaf(xv.x, w0.y, acc[i][1]);
                acc[i][2] = fmaf(xv.x, w0.z, acc[i][2]);
                acc[i][3] = fmaf(xv.x, w0.w, acc[i][3]);
                acc[i][0] = fmaf(xv.y, w1.x, acc[i][0]);
                acc[i][1] = fmaf(xv.y, w1.y, acc[i][1]);
                acc[i][2] = fmaf(xv.y, w1.z, acc[i][2]);
                acc[i][3] = fmaf(xv.y, w1.w, acc[i][3]);
                acc[i][0] = fmaf(xv.z, w2.x, acc[i][0]);
                acc[i][1] = fmaf(xv.z, w2.y, acc[i][1]);
                acc[i][2] = fmaf(xv.z, w2.z, acc[i][2]);
                acc[i][3] = fmaf(xv.z, w2.w, acc[i][3]);
                acc[i][0] = fmaf(xv.w, w3.x, acc[i][0]);
                acc[i][1] = fmaf(xv.w, w3.y, acc[i][1]);
                acc[i][2] = fmaf(xv.w, w3.z, acc[i][2]);
                acc[i][3] = fmaf(xv.w, w3.w, acc[i][3]);
            }
        }
    }

#pragma unroll
    for (int j = 0; j < 4; ++j) {
        float s1 = 0.f, s2 = 0.f;
#pragma unroll
        for (int i = 0; i < RPT; ++i) {
            int gr = rowbase + r0 + i;
            if (gr < N) {
                float y = acc[i][j];
                s1 += y;
                s2 += y * y;
            }
        }
        atomicAdd(&s_stats[0][4 * cg + j], s1);
        atomicAdd(&s_stats[1][4 * cg + j], s2);
    }
#pragma unroll
    for (int i = 0; i < RPT; ++i) {
        int gr = rowbase + r0 + i;
        if (gr < N) {
#pragma unroll
            for (int j = 0; j < CO; ++j)
                out[(size_t)gr * CO + j] = acc[i][j];
        }
    }
    __syncthreads();
    if (tid < CO) {
        atomicAdd(&stats[tid], s_stats[0][tid]);
        atomicAdd(&stats[64 + tid], s_stats[1][tid]);
    }
}

extern "C" void kernel_launch(void* const* d_in, const int* in_sizes, int n_in,
                              void* d_out, int out_size) {
    const int* nbr4  = (const int*)d_in[0];
    const int* inv43 = (const int*)d_in[1];
    const int* nbr3  = (const int*)d_in[2];
    const int* inv32 = (const int*)d_in[3];
    const int* nbr2  = (const int*)d_in[4];
    const int* inv21 = (const int*)d_in[5];
    const int* nbr1  = (const int*)d_in[6];
    const float* x   = (const float*)d_in[7];

    const float* W_m4 = (const float*)d_in[8];
    const float* g_m4 = (const float*)d_in[9];
    const float* b_m4 = (const float*)d_in[10];
    const float* W_i4 = (const float*)d_in[11];
    const float* g_i4 = (const float*)d_in[12];
    const float* b_i4 = (const float*)d_in[13];
    const float* W_m3 = (const float*)d_in[14];
    const float* g_m3 = (const float*)d_in[15];
    const float* b_m3 = (const float*)d_in[16];
    const float* W_i3 = (const float*)d_in[17];
    const float* g_i3 = (const float*)d_in[18];
    const float* b_i3 = (const float*)d_in[19];
    const float* W_m2 = (const float*)d_in[20];
    const float* g_m2 = (const float*)d_in[21];
    const float* b_m2 = (const float*)d_in[22];
    const float* W_i2 = (const float*)d_in[23];
    const float* g_i2 = (const float*)d_in[24];
    const float* b_i2 = (const float*)d_in[25];
    const float* W_m1 = (const float*)d_in[26];
    const float* g_m1 = (const float*)d_in[27];
    const float* b_m1 = (const float*)d_in[28];
    const float* W_c5 = (const float*)d_in[29];
    const float* g_c5 = (const float*)d_in[30];
    const float* b_c5 = (const float*)d_in[31];

    const int n4 = in_sizes[0] / 27;
    const int n3 = in_sizes[1] / 27;
    const int n2 = in_sizes[3] / 27;
    const int n1 = in_sizes[5] / 27;

    float *bufA, *bufB, *stats;
    cudaGetSymbolAddress((void**)&bufA, g_bufA);
    cudaGetSymbolAddress((void**)&bufB, g_bufB);
    cudaGetSymbolAddress((void**)&stats, g_stats);

    // smem sizes: TN*(CI+4)*4 + CI*CO*4
    constexpr int SM_L123 = (128 * 68 + 64 * 64) * 4;   // 51200, TN=128
    constexpr int SM_L4   = (128 * 68 + 64 * 32) * 4;   // 43008, TN=128
    constexpr int SM_L5   = (128 * 36 + 32 * 32) * 4;   // 22528, TN=128
    constexpr int SM_L6   = (256 * 36 + 32 * 16) * 4;   // 38912, TN=256
    constexpr int SM_L7   = (256 * 20 + 16 * 16) * 4;   // 21504, TN=256

    cudaFuncSetAttribute(gemm2_kernel<64, 64, 256, 4, 2>,
                         cudaFuncAttributeMaxDynamicSharedMemorySize, SM_L123);
    cudaFuncSetAttribute(gemm2_kernel<64, 32, 128, 4, 4>,
                         cudaFuncAttributeMaxDynamicSharedMemorySize, SM_L4);
    cudaFuncSetAttribute(gemm2_kernel<32, 32, 128, 4, 4>,
                         cudaFuncAttributeMaxDynamicSharedMemorySize, SM_L5);
    cudaFuncSetAttribute(gemm2_kernel<32, 16, 128, 4, 4>,
                         cudaFuncAttributeMaxDynamicSharedMemorySize, SM_L6);
    cudaFuncSetAttribute(gemm2_kernel<16, 16, 128, 4, 4>,
                         cudaFuncAttributeMaxDynamicSharedMemorySize, SM_L7);

    zero_stats_kernel<<<4, 256>>>();

    // L1: m4 (x -> A), 64->64, N=n4
    gemm2_kernel<64, 64, 256, 4, 2><<<(n4 + 127) / 128, 256, SM_L123>>>(
        x, nbr4, W_m4, bufA, stats + 0 * 128, n4);
    act_kernel<<<512, 256>>>(bufA, stats + 0 * 128, g_m4, b_m4, n4, 64);

    // L2: i4 (A -> B), 64->64, N=n3
    gemm2_kernel<64, 64, 256, 4, 2><<<(n3 + 127) / 128, 256, SM_L123>>>(
        bufA, inv43, W_i4, bufB, stats + 1 * 128, n3);
    act_kernel<<<512, 256>>>(bufB, stats + 1 * 128, g_i4, b_i4, n3, 64);

    // L3: m3 (B -> A), 64->64, N=n3
    gemm2_kernel<64, 64, 256, 4, 2><<<(n3 + 127) / 128, 256, SM_L123>>>(
        bufB, nbr3, W_m3, bufA, stats + 2 * 128, n3);
    act_kernel<<<512, 256>>>(bufA, stats + 2 * 128, g_m3, b_m3, n3, 64);

    // L4: i3 (A -> B), 64->32, N=n2
    gemm2_kernel<64, 32, 128, 4, 4><<<(n2 + 127) / 128, 128, SM_L4>>>(
        bufA, inv32, W_i3, bufB, stats + 3 * 128, n2);
    act_kernel<<<512, 256>>>(bufB, stats + 3 * 128, g_i3, b_i3, n2, 32);

    // L5: m2 (B -> A), 32->32, N=n2
    gemm2_kernel<32, 32, 128, 4, 4><<<(n2 + 127) / 128, 128, SM_L5>>>(
        bufB, nbr2, W_m2, bufA, stats + 4 * 128, n2);
    act_kernel<<<512, 256>>>(bufA, stats + 4 * 128, g_m2, b_m2, n2, 32);

    // L6: i2 (A -> B), 32->16, N=n1
    gemm2_kernel<32, 16, 128, 4, 4><<<(n1 + 255) / 256, 128, SM_L6>>>(
        bufA, inv21, W_i2, bufB, stats + 5 * 128, n1);
    act_kernel<<<512, 256>>>(bufB, stats + 5 * 128, g_i2, b_i2, n1, 16);

    // L7: m1 (B -> A), 16->16, N=n1
    gemm2_kernel<16, 16, 128, 4, 4><<<(n1 + 255) / 256, 128, SM_L7>>>(
        bufB, nbr1, W_m1, bufA, stats + 6 * 128, n1);
    act_kernel<<<512, 256>>>(bufA, stats + 6 * 128, g_m1, b_m1, n1, 16);

    // L8: c5 (A -> B raw), 16->3
    gemm_gather_kernel<16, 3, 4, 256, 1, 1>
        <<<(n1 + 255) / 256, 256>>>(bufA, nbr1, W_c5, bufB, stats + 7 * 128, n1);

    // final normalize (no relu)
    out_kernel<<<256, 256>>>(bufB, stats + 7 * 128, g_c5, b_c5,
                             (float*)d_out, n1);
}

// round 8
// speedup vs baseline: 1.3667x; 1.3016x over previous
#include <cuda_runtime.h>
#include <math.h>

// ---------------------------------------------------------------------------
// VoxelBackBone8x decoder: 8 x (gather-GEMM over 27 taps + BN + relu)
// R7: mask-sorted row permutation per layer -> warp-level tap skip becomes
//     near-exact (kills the 27-tap waste at L2..L7). f32x2 FFMA2 engine kept
//     from R6 (measured at ~88% of its pipe floor). Weight column split
//     {4cg, H+4cg} for conflict-free 128B weight LDS.
// ---------------------------------------------------------------------------

#define MAXROWS 102400
#define NB 1024

__device__ float g_bufA[MAXROWS * 64];
__device__ float g_bufB[MAXROWS * 64];
__device__ float g_stats[8 * 2 * 64];   // per layer: [sum(64), sumsq(64)]
__device__ int      g_perm[7][MAXROWS];
__device__ unsigned g_keys[MAXROWS];
__device__ unsigned g_hist[NB];
__device__ unsigned g_offs[NB];
__device__ unsigned g_cnt[NB];

__global__ void zero_stats_kernel() {
    int t = blockIdx.x * blockDim.x + threadIdx.x;
    if (t < 8 * 2 * 64) g_stats[t] = 0.f;
}

__global__ void zero_hist_kernel() {
    int t = blockIdx.x * blockDim.x + threadIdx.x;
    if (t < NB) { g_hist[t] = 0u; g_cnt[t] = 0u; }
}

// ---------------------------------------------------------------------------
// Permutation build: group rows by 27-bit tap-validity mask (hashed to NB
// buckets). Equal masks land adjacent -> tiles become tap-coherent.
// ---------------------------------------------------------------------------
__global__ void mask_hist_kernel(const int* __restrict__ nbr, int N,
                                 unsigned* __restrict__ keys,
                                 unsigned* __restrict__ hist) {
    __shared__ unsigned sh[NB];
    for (int i = threadIdx.x; i < NB; i += blockDim.x) sh[i] = 0;
    __syncthreads();
    int i = blockIdx.x * blockDim.x + threadIdx.x;
    if (i < N) {
        const int* row = nbr + (size_t)i * 27;
        unsigned m = 0;
#pragma unroll
        for (int k = 0; k < 27; ++k) m |= (row[k] >= 0 ? 1u : 0u) << k;
        unsigned key = (m * 2654435761u) >> 22;   // 10 bits
        keys[i] = key;
        atomicAdd(&sh[key], 1u);
    }
    __syncthreads();
    for (int j = threadIdx.x; j < NB; j += blockDim.x)
        if (sh[j]) atomicAdd(&hist[j], sh[j]);
}

__global__ void scan_kernel(const unsigned* __restrict__ hist,
                            unsigned* __restrict__ offs) {
    __shared__ unsigned s[NB];
    int t = threadIdx.x;
    unsigned h = hist[t];
    s[t] = h;
    __syncthreads();
    for (int d = 1; d < NB; d <<= 1) {
        unsigned v = (t >= d) ? s[t - d] : 0;
        __syncthreads();
        s[t] += v;
        __syncthreads();
    }
    offs[t] = s[t] - h;   // exclusive prefix
}

__global__ void scatter_kernel(const unsigned* __restrict__ keys,
                               const unsigned* __restrict__ offs,
                               unsigned* __restrict__ cnt,
                               int* __restrict__ perm, int N) {
    __shared__ unsigned bcnt[NB];
    __shared__ unsigned bbase[NB];
    for (int i = threadIdx.x; i < NB; i += blockDim.x) bcnt[i] = 0;
    __syncthreads();
    int i = blockIdx.x * blockDim.x + threadIdx.x;
    unsigned key = 0, rank = 0;
    bool valid = (i < N);
    if (valid) { key = keys[i]; rank = atomicAdd(&bcnt[key], 1u); }
    __syncthreads();
    for (int j = threadIdx.x; j < NB; j += blockDim.x)
        if (bcnt[j]) bbase[j] = atomicAdd(&cnt[j], bcnt[j]);
    __syncthreads();
    if (valid) perm[offs[key] + bbase[key] + rank] = i;
}

// ---------------------------------------------------------------------------
// f32x2 helpers
// ---------------------------------------------------------------------------
__device__ __forceinline__ void ffma2(unsigned long long& d, unsigned long long a,
                                      unsigned long long b) {
    asm("fma.rn.f32x2 %0, %1, %2, %0;" : "+l"(d) : "l"(a), "l"(b));
}
__device__ __forceinline__ unsigned long long packf2(float x) {
    unsigned long long r;
    unsigned int u = __float_as_uint(x);
    asm("mov.b64 %0, {%1, %1};" : "=l"(r) : "r"(u));
    return r;
}
__device__ __forceinline__ float2 unpackf2(unsigned long long v) {
    float2 f;
    asm("mov.b64 {%0, %1}, %2;" : "=f"(f.x), "=f"(f.y) : "l"(v));
    return f;
}

// ---------------------------------------------------------------------------
// In-place BN + relu: y = relu(y*a + b), affine computed from stats in-block.
// ---------------------------------------------------------------------------
__global__ void act_kernel(float* __restrict__ y, const float* __restrict__ stats,
                           const float* __restrict__ g, const float* __restrict__ b,
                           int N, int CO) {
    __shared__ float sa[64], sb[64];
    int c = threadIdx.x;
    if (c < CO) {
        float invN = 1.0f / (float)N;
        float mu = stats[c] * invN;
        float var = stats[64 + c] * invN - mu * mu;
        float a = g[c] * rsqrtf(var + 1e-3f);
        sa[c] = a;
        sb[c] = b[c] - mu * a;
    }
    __syncthreads();
    int total4 = N * CO / 4;
    int co4 = CO / 4;
    for (int i = blockIdx.x * blockDim.x + threadIdx.x; i < total4;
         i += gridDim.x * blockDim.x) {
        float4 v = ((float4*)y)[i];
        int cc = (i % co4) * 4;
        v.x = fmaxf(fmaf(v.x, sa[cc + 0], sb[cc + 0]), 0.f);
        v.y = fmaxf(fmaf(v.y, sa[cc + 1], sb[cc + 1]), 0.f);
        v.z = fmaxf(fmaf(v.z, sa[cc + 2], sb[cc + 2]), 0.f);
        v.w = fmaxf(fmaf(v.w, sa[cc + 3], sb[cc + 3]), 0.f);
        ((float4*)y)[i] = v;
    }
}

// final layer: out[n,3] = y[n,3]*a + b (no relu), affine from stats
__global__ void out_kernel(const float* __restrict__ y, const float* __restrict__ stats,
                           const float* __restrict__ g, const float* __restrict__ b,
                           float* __restrict__ out, int N) {
    __shared__ float sa[3], sb[3];
    int c = threadIdx.x;
    if (c < 3) {
        float invN = 1.0f / (float)N;
        float mu = stats[c] * invN;
        float var = stats[64 + c] * invN - mu * mu;
        float a = g[c] * rsqrtf(var + 1e-3f);
        sa[c] = a;
        sb[c] = b[c] - mu * a;
    }
    __syncthreads();
    int total = N * 3;
    for (int i = blockIdx.x * blockDim.x + threadIdx.x; i < total;
         i += gridDim.x * blockDim.x) {
        int j = i % 3;
        out[i] = fmaf(y[i], sa[j], sb[j]);
    }
}

// ---------------------------------------------------------------------------
// gemm2: gather-GEMM over mask-sorted rows. NT threads, per-thread tile =
// RPT rows x 8 cols (cols split {4cg..4cg+3, H+4cg..H+4cg+3}, H=CO/2).
// Per-warp tap skip at SUB-row granularity (exact after mask sorting).
// ---------------------------------------------------------------------------
template <int CI, int CO, int NT, int RPT, int MB>
__launch_bounds__(NT, MB)
__global__ void gemm2_kernel(const float* __restrict__ in,
                             const int* __restrict__ nbr,
                             const float* __restrict__ W,   // [27][CI][CO]
                             const int* __restrict__ perm,  // [N] sorted rows
                             float* __restrict__ out,       // [N][CO] raw
                             float* __restrict__ stats,     // [sum(64), sumsq(64)]
                             int N) {
    constexpr int G = CO / 8;
    constexpr int ROWG = NT / G;
    constexpr int TN = ROWG * RPT;
    constexpr int CIP = CI + 4;
    constexpr int SUB = (32 / G) * RPT;  // rows covered by one warp
    constexpr int NSUB = TN / SUB;
    constexpr int C4 = CI / 4;
    constexpr int H = CO / 2;

    extern __shared__ float smem[];
    float* s_x = smem;                   // TN * CIP
    float* s_w = smem + TN * CIP;        // CI * CO

    __shared__ int s_rows[TN];
    __shared__ int s_live[NSUB][27];
    __shared__ int s_flag[27];
    __shared__ float s_stats[2][CO];

    const int tid = threadIdx.x;
    const int rowbase = blockIdx.x * TN;

    for (int i = tid; i < NSUB * 27; i += NT) ((int*)s_live)[i] = 0;
    if (tid < CO) { s_stats[0][tid] = 0.f; s_stats[1][tid] = 0.f; }
    for (int i = tid; i < TN; i += NT) {
        int gr = rowbase + i;
        s_rows[i] = (gr < N) ? perm[gr] : -1;
    }
    __syncthreads();

    // liveness pre-pass (per SUB-row subset)
    for (int i = tid; i < TN * 27; i += NT) {
        int r = i / 27;
        int k = i - r * 27;
        int row = s_rows[r];
        if (row >= 0 && nbr[(size_t)row * 27 + k] >= 0) s_live[r / SUB][k] = 1;
    }
    __syncthreads();
    if (tid < 27) {
        int f = 0;
#pragma unroll
        for (int s = 0; s < NSUB; ++s) f |= s_live[s][tid];
        s_flag[tid] = f;
    }
    __syncthreads();

    const int cg = tid % G;
    const int rg = tid / G;
    const int r0 = rg * RPT;
    const int mysub = r0 / SUB;          // uniform within warp

    unsigned long long acc[RPT][4];
#pragma unroll
    for (int i = 0; i < RPT; ++i)
#pragma unroll
        for (int j = 0; j < 4; ++j) acc[i][j] = 0ULL;

    for (int k = 0; k < 27; ++k) {
        if (!s_flag[k]) continue;
        __syncthreads();   // previous tap's readers done

        // stage W[k]
        {
            const float4* Wk = (const float4*)(W + (size_t)k * CI * CO);
            for (int v = tid; v < CI * CO / 4; v += NT) ((float4*)s_w)[v] = Wk[v];
        }
        // gather features for this tap (skip dead SUB-row subsets)
        for (int v = tid; v < TN * C4; v += NT) {
            int r = v / C4;
            int c4 = v - r * C4;
            if (!s_live[r / SUB][k]) continue;
            int row = s_rows[r];
            int idx = (row >= 0) ? nbr[(size_t)row * 27 + k] : -1;
            float4 val = make_float4(0.f, 0.f, 0.f, 0.f);
            if (idx >= 0) val = *(const float4*)(in + (size_t)idx * CI + c4 * 4);
            *(float4*)(s_x + r * CIP + c4 * 4) = val;
        }
        __syncthreads();

        if (!s_live[mysub][k]) continue;  // per-warp skip (no syncs below)

#pragma unroll 2
        for (int c = 0; c < CI; c += 2) {
            ulonglong2 wa0 = *(const ulonglong2*)(s_w + (c + 0) * CO + 4 * cg);
            ulonglong2 wa1 = *(const ulonglong2*)(s_w + (c + 0) * CO + H + 4 * cg);
            ulonglong2 wb0 = *(const ulonglong2*)(s_w + (c + 1) * CO + 4 * cg);
            ulonglong2 wb1 = *(const ulonglong2*)(s_w + (c + 1) * CO + H + 4 * cg);
#pragma unroll
            for (int i = 0; i < RPT; ++i) {
                float2 xv = *(const float2*)(s_x + (r0 + i) * CIP + c);
                unsigned long long xa = packf2(xv.x);
                unsigned long long xb = packf2(xv.y);
                ffma2(acc[i][0], xa, wa0.x);
                ffma2(acc[i][1], xa, wa0.y);
                ffma2(acc[i][2], xa, wa1.x);
                ffma2(acc[i][3], xa, wa1.y);
                ffma2(acc[i][0], xb, wb0.x);
                ffma2(acc[i][1], xb, wb0.y);
                ffma2(acc[i][2], xb, wb1.x);
                ffma2(acc[i][3], xb, wb1.y);
            }
        }
    }

    // epilogue: store raw y + accumulate stats
    // acc[i][0]: cols 4cg..+1, [1]: 4cg+2..+3, [2]: H+4cg..+1, [3]: H+4cg+2..+3
#pragma unroll
    for (int j = 0; j < 4; ++j) {
        float s1 = 0.f, s2 = 0.f, t1 = 0.f, t2 = 0.f;
#pragma unroll
        for (int i = 0; i < RPT; ++i) {
            if (s_rows[r0 + i] >= 0) {
                float2 p = unpackf2(acc[i][j]);
                s1 += p.x; s2 += p.x * p.x;
                t1 += p.y; t2 += p.y * p.y;
            }
        }
        int base = (j < 2) ? (4 * cg + 2 * j) : (H + 4 * cg + 2 * (j - 2));
        atomicAdd(&s_stats[0][base + 0], s1);
        atomicAdd(&s_stats[1][base + 0], s2);
        atomicAdd(&s_stats[0][base + 1], t1);
        atomicAdd(&s_stats[1][base + 1], t2);
    }
#pragma unroll
    for (int i = 0; i < RPT; ++i) {
        int row = s_rows[r0 + i];
        if (row >= 0) {
            float2 p0 = unpackf2(acc[i][0]);
            float2 p1 = unpackf2(acc[i][1]);
            float2 p2 = unpackf2(acc[i][2]);
            float2 p3 = unpackf2(acc[i][3]);
            *(float4*)(out + (size_t)row * CO + 4 * cg) =
                make_float4(p0.x, p0.y, p1.x, p1.y);
            *(float4*)(out + (size_t)row * CO + H + 4 * cg) =
                make_float4(p2.x, p2.y, p3.x, p3.y);
        }
    }
    __syncthreads();
    if (tid < CO) {
        atomicAdd(&stats[tid], s_stats[0][tid]);
        atomicAdd(&stats[64 + tid], s_stats[1][tid]);
    }
}

// ---------------------------------------------------------------------------
// Old-style scalar kernel, kept only for the tiny 16->3 final conv.
// ---------------------------------------------------------------------------
template <int CI, int CO, int COP, int TN, int G, int RPT>
__launch_bounds__(256, 2)
__global__ void gemm_gather_kernel(const float* __restrict__ in,
                                   const int* __restrict__ nbr,
                                   const float* __restrict__ W,
                                   float* __restrict__ out,
                                   float* __restrict__ stats,
                                   int N) {
    constexpr int CIP = CI + 4;

    __shared__ float s_x[TN * CIP];
    __shared__ float s_w[CI * COP];
    __shared__ int   s_nbr[TN * 27];
    __shared__ int   s_flag[27];
    __shared__ float s_stats[2][COP];

    const int tid = threadIdx.x;
    const int rowbase = blockIdx.x * TN;

    if (tid < 27) s_flag[tid] = 0;
    if (tid < COP) { s_stats[0][tid] = 0.f; s_stats[1][tid] = 0.f; }
    __syncthreads();

    for (int i = tid; i < TN * 27; i += 256) {
        int r = i / 27;
        int k = i - r * 27;
        int gr = rowbase + r;
        int v = (gr < N) ? nbr[gr * 27 + k] : -1;
        s_nbr[i] = v;
        if (v >= 0) s_flag[k] = 1;
    }
    __syncthreads();

    const int cg = tid % G;
    const int rg = tid / G;
    const int r0 = rg * RPT;

    float acc[RPT][4];
#pragma unroll
    for (int i = 0; i < RPT; ++i)
#pragma unroll
        for (int j = 0; j < 4; ++j) acc[i][j] = 0.f;

    for (int k = 0; k < 27; ++k) {
        if (!s_flag[k]) continue;
        __syncthreads();

        {
            const float* Wk = W + (size_t)k * CI * CO;
            for (int v = tid; v < CI * COP; v += 256) {
                int c = v / COP, j = v - c * COP;
                s_w[v] = (j < CO) ? Wk[c * CO + j] : 0.f;
            }
        }

        for (int v = tid; v < TN * CI / 4; v += 256) {
            int r = v / (CI / 4);
            int c4 = v - r * (CI / 4);
            int idx = s_nbr[r * 27 + k];
            float4 val = make_float4(0.f, 0.f, 0.f, 0.f);
            if (idx >= 0)
                val = *(const float4*)(in + (size_t)idx * CI + c4 * 4);
            *(float4*)(s_x + r * CIP + c4 * 4) = val;
        }
        __syncthreads();

#pragma unroll
        for (int c = 0; c < CI; c += 4) {
            float4 w0 = *(const float4*)(s_w + (c + 0) * COP + 4 * cg);
            float4 w1 = *(const float4*)(s_w + (c + 1) * COP + 4 * cg);
            float4 w2 = *(const float4*)(s_w + (c + 2) * COP + 4 * cg);
            float4 w3 = *(const float4*)(s_w + (c + 3) * COP + 4 * cg);
#pragma unroll
            for (int i = 0; i < RPT; ++i) {
                float4 xv = *(const float4*)(s_x + (r0 + i) * CIP + c);
                acc[i][0] = fmaf(xv.x, w0.x, acc[i][0]);
                acc[i][1] = fmaf(xv.x, w0.y, acc[i][1]);
                acc[i][2] = fmaf(xv.x, w0.z, acc[i][2]);
                acc[i][3] = fmaf(xv.x, w0.w, acc[i][3]);
                acc[i][0] = fmaf(xv.y, w1.x, acc[i][0]);
                acc[i][1] = fmaf(xv.y, w1.y, acc[i][1]);
                acc[i][2] = fmaf(xv.y, w1.z, acc[i][2]);
                acc[i][3] = fmaf(xv.y, w1.w, acc[i][3]);
                acc[i][0] = fmaf(xv.z, w2.x, acc[i][0]);
                acc[i][1] = fmaf(xv.z, w2.y, acc[i][1]);
                acc[i][2] = fmaf(xv.z, w2.z, acc[i][2]);
                acc[i][3] = fmaf(xv.z, w2.w, acc[i][3]);
                acc[i][0] = fmaf(xv.w, w3.x, acc[i][0]);
                acc[i][1] = fmaf(xv.w, w3.y, acc[i][1]);
                acc[i][2] = fmaf(xv.w, w3.z, acc[i][2]);
                acc[i][3] = fmaf(xv.w, w3.w, acc[i][3]);
            }
        }
    }

#pragma unroll
    for (int j = 0; j < 4; ++j) {
        float s1 = 0.f, s2 = 0.f;
#pragma unroll
        for (int i = 0; i < RPT; ++i) {
            int gr = rowbase + r0 + i;
            if (gr < N) {
                float y = acc[i][j];
                s1 += y;
                s2 += y * y;
            }
        }
        atomicAdd(&s_stats[0][4 * cg + j], s1);
        atomicAdd(&s_stats[1][4 * cg + j], s2);
    }
#pragma unroll
    for (int i = 0; i < RPT; ++i) {
        int gr = rowbase + r0 + i;
        if (gr < N) {
#pragma unroll
            for (int j = 0; j < CO; ++j)
                out[(size_t)gr * CO + j] = acc[i][j];
        }
    }
    __syncthreads();
    if (tid < CO) {
        atomicAdd(&stats[tid], s_stats[0][tid]);
        atomicAdd(&stats[64 + tid], s_stats[1][tid]);
    }
}

extern "C" void kernel_launch(void* const* d_in, const int* in_sizes, int n_in,
                              void* d_out, int out_size) {
    const int* nbr4  = (const int*)d_in[0];
    const int* inv43 = (const int*)d_in[1];
    const int* nbr3  = (const int*)d_in[2];
    const int* inv32 = (const int*)d_in[3];
    const int* nbr2  = (const int*)d_in[4];
    const int* inv21 = (const int*)d_in[5];
    const int* nbr1  = (const int*)d_in[6];
    const float* x   = (const float*)d_in[7];

    const float* W_m4 = (const float*)d_in[8];
    const float* g_m4 = (const float*)d_in[9];
    const float* b_m4 = (const float*)d_in[10];
    const float* W_i4 = (const float*)d_in[11];
    const float* g_i4 = (const float*)d_in[12];
    const float* b_i4 = (const float*)d_in[13];
    const float* W_m3 = (const float*)d_in[14];
    const float* g_m3 = (const float*)d_in[15];
    const float* b_m3 = (const float*)d_in[16];
    const float* W_i3 = (const float*)d_in[17];
    const float* g_i3 = (const float*)d_in[18];
    const float* b_i3 = (const float*)d_in[19];
    const float* W_m2 = (const float*)d_in[20];
    const float* g_m2 = (const float*)d_in[21];
    const float* b_m2 = (const float*)d_in[22];
    const float* W_i2 = (const float*)d_in[23];
    const float* g_i2 = (const float*)d_in[24];
    const float* b_i2 = (const float*)d_in[25];
    const float* W_m1 = (const float*)d_in[26];
    const float* g_m1 = (const float*)d_in[27];
    const float* b_m1 = (const float*)d_in[28];
    const float* W_c5 = (const float*)d_in[29];
    const float* g_c5 = (const float*)d_in[30];
    const float* b_c5 = (const float*)d_in[31];

    const int n4 = in_sizes[0] / 27;
    const int n3 = in_sizes[1] / 27;
    const int n2 = in_sizes[3] / 27;
    const int n1 = in_sizes[5] / 27;

    float *bufA, *bufB, *stats;
    int* perm;
    unsigned *keys, *hist, *offs, *cnt;
    cudaGetSymbolAddress((void**)&bufA, g_bufA);
    cudaGetSymbolAddress((void**)&bufB, g_bufB);
    cudaGetSymbolAddress((void**)&stats, g_stats);
    cudaGetSymbolAddress((void**)&perm, g_perm);
    cudaGetSymbolAddress((void**)&keys, g_keys);
    cudaGetSymbolAddress((void**)&hist, g_hist);
    cudaGetSymbolAddress((void**)&offs, g_offs);
    cudaGetSymbolAddress((void**)&cnt, g_cnt);

    // smem sizes: TN*(CI+4)*4 + CI*CO*4
    constexpr int SM_L123 = (128 * 68 + 64 * 64) * 4;   // TN=128
    constexpr int SM_L4   = (128 * 68 + 64 * 32) * 4;   // TN=128
    constexpr int SM_L5   = (128 * 36 + 32 * 32) * 4;   // TN=128
    constexpr int SM_L6   = (256 * 36 + 32 * 16) * 4;   // TN=256
    constexpr int SM_L7   = (256 * 20 + 16 * 16) * 4;   // TN=256

    cudaFuncSetAttribute(gemm2_kernel<64, 64, 256, 4, 2>,
                         cudaFuncAttributeMaxDynamicSharedMemorySize, SM_L123);
    cudaFuncSetAttribute(gemm2_kernel<64, 32, 128, 4, 4>,
                         cudaFuncAttributeMaxDynamicSharedMemorySize, SM_L4);
    cudaFuncSetAttribute(gemm2_kernel<32, 32, 128, 4, 4>,
                         cudaFuncAttributeMaxDynamicSharedMemorySize, SM_L5);
    cudaFuncSetAttribute(gemm2_kernel<32, 16, 128, 4, 4>,
                         cudaFuncAttributeMaxDynamicSharedMemorySize, SM_L6);
    cudaFuncSetAttribute(gemm2_kernel<16, 16, 128, 4, 4>,
                         cudaFuncAttributeMaxDynamicSharedMemorySize, SM_L7);

    // ---- build mask-sorted permutations for the 7 permuted conv layers ----
    const int* tabs[7] = {nbr4, inv43, nbr3, inv32, nbr2, inv21, nbr1};
    const int  ns[7]   = {n4,   n3,    n3,   n2,    n2,   n1,    n1};
    for (int l = 0; l < 7; ++l) {
        zero_hist_kernel<<<4, 256>>>();
        mask_hist_kernel<<<(ns[l] + 255) / 256, 256>>>(tabs[l], ns[l], keys, hist);
        scan_kernel<<<1, NB>>>(hist, offs);
        scatter_kernel<<<(ns[l] + 255) / 256, 256>>>(keys, offs, cnt,
                                                     perm + l * MAXROWS, ns[l]);
    }

    zero_stats_kernel<<<4, 256>>>();

    // L1: m4 (x -> A), 64->64, N=n4
    gemm2_kernel<64, 64, 256, 4, 2><<<(n4 + 127) / 128, 256, SM_L123>>>(
        x, nbr4, W_m4, perm + 0 * MAXROWS, bufA, stats + 0 * 128, n4);
    act_kernel<<<512, 256>>>(bufA, stats + 0 * 128, g_m4, b_m4, n4, 64);

    // L2: i4 (A -> B), 64->64, N=n3
    gemm2_kernel<64, 64, 256, 4, 2><<<(n3 + 127) / 128, 256, SM_L123>>>(
        bufA, inv43, W_i4, perm + 1 * MAXROWS, bufB, stats + 1 * 128, n3);
    act_kernel<<<512, 256>>>(bufB, stats + 1 * 128, g_i4, b_i4, n3, 64);

    // L3: m3 (B -> A), 64->64, N=n3
    gemm2_kernel<64, 64, 256, 4, 2><<<(n3 + 127) / 128, 256, SM_L123>>>(
        bufB, nbr3, W_m3, perm + 2 * MAXROWS, bufA, stats + 2 * 128, n3);
    act_kernel<<<512, 256>>>(bufA, stats + 2 * 128, g_m3, b_m3, n3, 64);

    // L4: i3 (A -> B), 64->32, N=n2
    gemm2_kernel<64, 32, 128, 4, 4><<<(n2 + 127) / 128, 128, SM_L4>>>(
        bufA, inv32, W_i3, perm + 3 * MAXROWS, bufB, stats + 3 * 128, n2);
    act_kernel<<<512, 256>>>(bufB, stats + 3 * 128, g_i3, b_i3, n2, 32);

    // L5: m2 (B -> A), 32->32, N=n2
    gemm2_kernel<32, 32, 128, 4, 4><<<(n2 + 127) / 128, 128, SM_L5>>>(
        bufB, nbr2, W_m2, perm + 4 * MAXROWS, bufA, stats + 4 * 128, n2);
    act_kernel<<<512, 256>>>(bufA, stats + 4 * 128, g_m2, b_m2, n2, 32);

    // L6: i2 (A -> B), 32->16, N=n1
    gemm2_kernel<32, 16, 128, 4, 4><<<(n1 + 255) / 256, 128, SM_L6>>>(
        bufA, inv21, W_i2, perm + 5 * MAXROWS, bufB, stats + 5 * 128, n1);
    act_kernel<<<512, 256>>>(bufB, stats + 5 * 128, g_i2, b_i2, n1, 16);

    // L7: m1 (B -> A), 16->16, N=n1
    gemm2_kernel<16, 16, 128, 4, 4><<<(n1 + 255) / 256, 128, SM_L7>>>(
        bufB, nbr1, W_m1, perm + 6 * MAXROWS, bufA, stats + 6 * 128, n1);
    act_kernel<<<512, 256>>>(bufA, stats + 6 * 128, g_m1, b_m1, n1, 16);

    // L8: c5 (A -> B raw), 16->3
    gemm_gather_kernel<16, 3, 4, 256, 1, 1>
        <<<(n1 + 255) / 256, 256>>>(bufA, nbr1, W_c5, bufB, stats + 7 * 128, n1);

    // final normalize (no relu)
    out_kernel<<<256, 256>>>(bufB, stats + 7 * 128, g_c5, b_c5,
                             (float*)d_out, n1);
}

// round 9
// speedup vs baseline: 1.4120x; 1.0331x over previous
#include <cuda_runtime.h>
#include <math.h>

// ---------------------------------------------------------------------------
// VoxelBackBone8x decoder: 8 x (gather-GEMM over 27 taps + BN + relu)
// R8: fused perm build (4 launches for all 7 layers), lazy BN applied in-gather
//     (finalize kernel -> affine; no act passes), L8 gets perm + per-warp skip.
//     Launch order puts L1 gemm at index 5 so ncu (-s 5 -c 1) captures it.
// ---------------------------------------------------------------------------

#define MAXROWS 102400
#define NB 1024

__device__ float g_bufA[MAXROWS * 64];
__device__ float g_bufB[MAXROWS * 64];
__device__ float g_stats[8 * 2 * 64];   // per layer: [sum(64), sumsq(64)]
__device__ float g_aff[8 * 2 * 64];     // per layer: [a(64), b(64)]
__device__ int      g_perm[7][MAXROWS];
__device__ unsigned g_keys[7][MAXROWS];
__device__ unsigned g_hist[7 * NB];
__device__ unsigned g_offs[7 * NB];
__device__ unsigned g_cnt[7 * NB];

struct PermArgs {
    const int* tab[7];
    int n[7];
    int cum[8];   // cumulative block counts (256-thread blocks)
};

__global__ void zero_hist_all_kernel() {
    int t = blockIdx.x * blockDim.x + threadIdx.x;
    if (t < 7 * NB) { g_hist[t] = 0u; g_cnt[t] = 0u; }
}

__global__ void zero_stats_kernel() {
    int t = blockIdx.x * blockDim.x + threadIdx.x;
    if (t < 8 * 2 * 64) g_stats[t] = 0.f;
}

// ---------------------------------------------------------------------------
// Fused permutation build over all 7 layers.
// ---------------------------------------------------------------------------
__global__ void mask_hist_all_kernel(PermArgs pa) {
    __shared__ unsigned sh[NB];
    __shared__ int s_l;
    for (int i = threadIdx.x; i < NB; i += blockDim.x) sh[i] = 0;
    if (threadIdx.x == 0) {
        int l = 0;
        while (blockIdx.x >= (unsigned)pa.cum[l + 1]) ++l;
        s_l = l;
    }
    __syncthreads();
    int l = s_l;
    int i = (blockIdx.x - pa.cum[l]) * 256 + threadIdx.x;
    if (i < pa.n[l]) {
        const int* row = pa.tab[l] + (size_t)i * 27;
        unsigned m = 0;
#pragma unroll
        for (int k = 0; k < 27; ++k) m |= (row[k] >= 0 ? 1u : 0u) << k;
        unsigned key = (m * 2654435761u) >> 22;   // 10 bits
        g_keys[l][i] = key;
        atomicAdd(&sh[key], 1u);
    }
    __syncthreads();
    for (int j = threadIdx.x; j < NB; j += blockDim.x)
        if (sh[j]) atomicAdd(&g_hist[l * NB + j], sh[j]);
}

__global__ void scan_all_kernel() {   // grid = 7, block = NB
    __shared__ unsigned s[NB];
    int l = blockIdx.x;
    int t = threadIdx.x;
    unsigned h = g_hist[l * NB + t];
    s[t] = h;
    __syncthreads();
    for (int d = 1; d < NB; d <<= 1) {
        unsigned v = (t >= d) ? s[t - d] : 0;
        __syncthreads();
        s[t] += v;
        __syncthreads();
    }
    g_offs[l * NB + t] = s[t] - h;   // exclusive prefix
}

__global__ void scatter_all_kernel(PermArgs pa) {
    __shared__ unsigned bcnt[NB];
    __shared__ unsigned bbase[NB];
    __shared__ int s_l;
    for (int i = threadIdx.x; i < NB; i += blockDim.x) bcnt[i] = 0;
    if (threadIdx.x == 0) {
        int l = 0;
        while (blockIdx.x >= (unsigned)pa.cum[l + 1]) ++l;
        s_l = l;
    }
    __syncthreads();
    int l = s_l;
    int i = (blockIdx.x - pa.cum[l]) * 256 + threadIdx.x;
    unsigned key = 0, rank = 0;
    bool valid = (i < pa.n[l]);
    if (valid) { key = g_keys[l][i]; rank = atomicAdd(&bcnt[key], 1u); }
    __syncthreads();
    for (int j = threadIdx.x; j < NB; j += blockDim.x)
        if (bcnt[j]) bbase[j] = atomicAdd(&g_cnt[l * NB + j], bcnt[j]);
    __syncthreads();
    if (valid) g_perm[l][g_offs[l * NB + key] + bbase[key] + rank] = i;
}

// ---------------------------------------------------------------------------
// f32x2 helpers
// ---------------------------------------------------------------------------
__device__ __forceinline__ void ffma2(unsigned long long& d, unsigned long long a,
                                      unsigned long long b) {
    asm("fma.rn.f32x2 %0, %1, %2, %0;" : "+l"(d) : "l"(a), "l"(b));
}
__device__ __forceinline__ unsigned long long packf2(float x) {
    unsigned long long r;
    unsigned int u = __float_as_uint(x);
    asm("mov.b64 %0, {%1, %1};" : "=l"(r) : "r"(u));
    return r;
}
__device__ __forceinline__ float2 unpackf2(unsigned long long v) {
    float2 f;
    asm("mov.b64 {%0, %1}, %2;" : "=f"(f.x), "=f"(f.y) : "l"(v));
    return f;
}

// ---------------------------------------------------------------------------
// finalize: stats -> affine (a, b) for one layer
// ---------------------------------------------------------------------------
__global__ void finalize_kernel(const float* __restrict__ stats,
                                const float* __restrict__ g,
                                const float* __restrict__ b,
                                float* __restrict__ aff, int N, int CO) {
    int c = threadIdx.x;
    if (c < CO) {
        float invN = 1.0f / (float)N;
        float mu = stats[c] * invN;
        float var = stats[64 + c] * invN - mu * mu;
        float a = g[c] * rsqrtf(var + 1e-3f);
        aff[c] = a;
        aff[64 + c] = b[c] - mu * a;
    }
}

// final layer: out[n,3] = y[n,3]*a + b (no relu), affine from stats
__global__ void out_kernel(const float* __restrict__ y, const float* __restrict__ stats,
                           const float* __restrict__ g, const float* __restrict__ b,
                           float* __restrict__ out, int N) {
    __shared__ float sa[3], sb[3];
    int c = threadIdx.x;
    if (c < 3) {
        float invN = 1.0f / (float)N;
        float mu = stats[c] * invN;
        float var = stats[64 + c] * invN - mu * mu;
        float a = g[c] * rsqrtf(var + 1e-3f);
        sa[c] = a;
        sb[c] = b[c] - mu * a;
    }
    __syncthreads();
    int total = N * 3;
    for (int i = blockIdx.x * blockDim.x + threadIdx.x; i < total;
         i += gridDim.x * blockDim.x) {
        int j = i % 3;
        out[i] = fmaf(y[i], sa[j], sb[j]);
    }
}

// ---------------------------------------------------------------------------
// gemm2: gather-GEMM over mask-sorted rows. NT threads, per-thread tile =
// RPT rows x 8 cols (cols split {4cg, H+4cg}, H=CO/2). Per-warp tap skip at
// SUB-row granularity. APPLY: relu(v*a+b) of PREVIOUS layer during gather.
// ---------------------------------------------------------------------------
template <int CI, int CO, int NT, int RPT, int MB, bool APPLY>
__launch_bounds__(NT, MB)
__global__ void gemm2_kernel(const float* __restrict__ in,
                             const int* __restrict__ nbr,
                             const float* __restrict__ W,   // [27][CI][CO]
                             const int* __restrict__ perm,  // [N] sorted rows
                             const float* __restrict__ aff, // [a(64), b(64)]
                             float* __restrict__ out,       // [N][CO] raw
                             float* __restrict__ stats,     // [sum(64), sumsq(64)]
                             int N) {
    constexpr int G = CO / 8;
    constexpr int ROWG = NT / G;
    constexpr int TN = ROWG * RPT;
    constexpr int CIP = CI + 4;
    constexpr int SUB = (32 / G) * RPT;  // rows covered by one warp
    constexpr int NSUB = TN / SUB;
    constexpr int C4 = CI / 4;
    constexpr int H = CO / 2;

    extern __shared__ float smem[];
    float* s_x = smem;                   // TN * CIP
    float* s_w = smem + TN * CIP;        // CI * CO

    __shared__ int s_rows[TN];
    __shared__ int s_live[NSUB][27];
    __shared__ int s_flag[27];
    __shared__ float s_stats[2][CO];
    __shared__ float s_a[CI], s_b[CI];

    const int tid = threadIdx.x;
    const int rowbase = blockIdx.x * TN;

    for (int i = tid; i < NSUB * 27; i += NT) ((int*)s_live)[i] = 0;
    if (tid < CO) { s_stats[0][tid] = 0.f; s_stats[1][tid] = 0.f; }
    if (APPLY) {
        for (int c = tid; c < CI; c += NT) {
            s_a[c] = aff[c];
            s_b[c] = aff[64 + c];
        }
    }
    for (int i = tid; i < TN; i += NT) {
        int gr = rowbase + i;
        s_rows[i] = (gr < N) ? perm[gr] : -1;
    }
    __syncthreads();

    // liveness pre-pass (per SUB-row subset)
    for (int i = tid; i < TN * 27; i += NT) {
        int r = i / 27;
        int k = i - r * 27;
        int row = s_rows[r];
        if (row >= 0 && nbr[(size_t)row * 27 + k] >= 0) s_live[r / SUB][k] = 1;
    }
    __syncthreads();
    if (tid < 27) {
        int f = 0;
#pragma unroll
        for (int s = 0; s < NSUB; ++s) f |= s_live[s][tid];
        s_flag[tid] = f;
    }
    __syncthreads();

    const int cg = tid % G;
    const int rg = tid / G;
    const int r0 = rg * RPT;
    const int mysub = r0 / SUB;          // uniform within warp

    unsigned long long acc[RPT][4];
#pragma unroll
    for (int i = 0; i < RPT; ++i)
#pragma unroll
        for (int j = 0; j < 4; ++j) acc[i][j] = 0ULL;

    for (int k = 0; k < 27; ++k) {
        if (!s_flag[k]) continue;
        __syncthreads();   // previous tap's readers done

        // stage W[k]
        {
            const float4* Wk = (const float4*)(W + (size_t)k * CI * CO);
            for (int v = tid; v < CI * CO / 4; v += NT) ((float4*)s_w)[v] = Wk[v];
        }
        // gather features for this tap (skip dead SUB-row subsets),
        // applying previous layer's BN+relu in flight
        for (int v = tid; v < TN * C4; v += NT) {
            int r = v / C4;
            int c4 = v - r * C4;
            if (!s_live[r / SUB][k]) continue;
            int row = s_rows[r];
            int idx = (row >= 0) ? nbr[(size_t)row * 27 + k] : -1;
            float4 val = make_float4(0.f, 0.f, 0.f, 0.f);
            if (idx >= 0) {
                val = *(const float4*)(in + (size_t)idx * CI + c4 * 4);
                if (APPLY) {
                    int c = c4 * 4;
                    val.x = fmaxf(fmaf(val.x, s_a[c + 0], s_b[c + 0]), 0.f);
                    val.y = fmaxf(fmaf(val.y, s_a[c + 1], s_b[c + 1]), 0.f);
                    val.z = fmaxf(fmaf(val.z, s_a[c + 2], s_b[c + 2]), 0.f);
                    val.w = fmaxf(fmaf(val.w, s_a[c + 3], s_b[c + 3]), 0.f);
                }
            }
            *(float4*)(s_x + r * CIP + c4 * 4) = val;
        }
        __syncthreads();

        if (!s_live[mysub][k]) continue;  // per-warp skip (no syncs below)

#pragma unroll 2
        for (int c = 0; c < CI; c += 2) {
            ulonglong2 wa0 = *(const ulonglong2*)(s_w + (c + 0) * CO + 4 * cg);
            ulonglong2 wa1 = *(const ulonglong2*)(s_w + (c + 0) * CO + H + 4 * cg);
            ulonglong2 wb0 = *(const ulonglong2*)(s_w + (c + 1) * CO + 4 * cg);
            ulonglong2 wb1 = *(const ulonglong2*)(s_w + (c + 1) * CO + H + 4 * cg);
#pragma unroll
            for (int i = 0; i < RPT; ++i) {
                float2 xv = *(const float2*)(s_x + (r0 + i) * CIP + c);
                unsigned long long xa = packf2(xv.x);
                unsigned long long xb = packf2(xv.y);
                ffma2(acc[i][0], xa, wa0.x);
                ffma2(acc[i][1], xa, wa0.y);
                ffma2(acc[i][2], xa, wa1.x);
                ffma2(acc[i][3], xa, wa1.y);
                ffma2(acc[i][0], xb, wb0.x);
                ffma2(acc[i][1], xb, wb0.y);
                ffma2(acc[i][2], xb, wb1.x);
                ffma2(acc[i][3], xb, wb1.y);
            }
        }
    }

    // epilogue: store raw y + accumulate stats
#pragma unroll
    for (int j = 0; j < 4; ++j) {
        float s1 = 0.f, s2 = 0.f, t1 = 0.f, t2 = 0.f;
#pragma unroll
        for (int i = 0; i < RPT; ++i) {
            if (s_rows[r0 + i] >= 0) {
                float2 p = unpackf2(acc[i][j]);
                s1 += p.x; s2 += p.x * p.x;
                t1 += p.y; t2 += p.y * p.y;
            }
        }
        int base = (j < 2) ? (4 * cg + 2 * j) : (H + 4 * cg + 2 * (j - 2));
        atomicAdd(&s_stats[0][base + 0], s1);
        atomicAdd(&s_stats[1][base + 0], s2);
        atomicAdd(&s_stats[0][base + 1], t1);
        atomicAdd(&s_stats[1][base + 1], t2);
    }
#pragma unroll
    for (int i = 0; i < RPT; ++i) {
        int row = s_rows[r0 + i];
        if (row >= 0) {
            float2 p0 = unpackf2(acc[i][0]);
            float2 p1 = unpackf2(acc[i][1]);
            float2 p2 = unpackf2(acc[i][2]);
            float2 p3 = unpackf2(acc[i][3]);
            *(float4*)(out + (size_t)row * CO + 4 * cg) =
                make_float4(p0.x, p0.y, p1.x, p1.y);
            *(float4*)(out + (size_t)row * CO + H + 4 * cg) =
                make_float4(p2.x, p2.y, p3.x, p3.y);
        }
    }
    __syncthreads();
    if (tid < CO) {
        atomicAdd(&stats[tid], s_stats[0][tid]);
        atomicAdd(&stats[64 + tid], s_stats[1][tid]);
    }
}

// ---------------------------------------------------------------------------
// Final 16->3 conv: perm-sorted rows, per-warp (32-row) tap skip, in-gather
// apply of layer-7 affine. 256 threads, 1 row/thread, 3 cols.
// ---------------------------------------------------------------------------
__launch_bounds__(256, 4)
__global__ void gemm_c5_kernel(const float* __restrict__ in,
                               const int* __restrict__ nbr,
                               const float* __restrict__ W,     // [27][16][3]
                               const int* __restrict__ perm,
                               const float* __restrict__ aff,   // layer-7 affine
                               float* __restrict__ out,         // [N][3] raw
                               float* __restrict__ stats,
                               int N) {
    constexpr int CI = 16, CO = 3, COP = 4, TN = 256, CIP = CI + 4;
    constexpr int SUB = 32, NSUB = TN / SUB;

    __shared__ float s_x[TN * CIP];
    __shared__ float s_w[CI * COP];
    __shared__ int   s_rows[TN];
    __shared__ int   s_live[NSUB][27];
    __shared__ int   s_flag[27];
    __shared__ float s_stats[2][COP];
    __shared__ float s_a[CI], s_b[CI];

    const int tid = threadIdx.x;
    const int rowbase = blockIdx.x * TN;

    for (int i = tid; i < NSUB * 27; i += 256) ((int*)s_live)[i] = 0;
    if (tid < COP) { s_stats[0][tid] = 0.f; s_stats[1][tid] = 0.f; }
    if (tid < CI) { s_a[tid] = aff[tid]; s_b[tid] = aff[64 + tid]; }
    {
        int gr = rowbase + tid;
        s_rows[tid] = (gr < N) ? perm[gr] : -1;
    }
    __syncthreads();

    for (int i = tid; i < TN * 27; i += 256) {
        int r = i / 27;
        int k = i - r * 27;
        int row = s_rows[r];
        if (row >= 0 && nbr[(size_t)row * 27 + k] >= 0) s_live[r / SUB][k] = 1;
    }
    __syncthreads();
    if (tid < 27) {
        int f = 0;
#pragma unroll
        for (int s = 0; s < NSUB; ++s) f |= s_live[s][tid];
        s_flag[tid] = f;
    }
    __syncthreads();

    const int mysub = tid / SUB;

    float acc[3] = {0.f, 0.f, 0.f};

    for (int k = 0; k < 27; ++k) {
        if (!s_flag[k]) continue;
        __syncthreads();

        {
            const float* Wk = W + (size_t)k * CI * CO;
            for (int v = tid; v < CI * COP; v += 256) {
                int c = v / COP, j = v - c * COP;
                s_w[v] = (j < CO) ? Wk[c * CO + j] : 0.f;
            }
        }
        for (int v = tid; v < TN * (CI / 4); v += 256) {
            int r = v / (CI / 4);
            int c4 = v - r * (CI / 4);
            if (!s_live[r / SUB][k]) continue;
            int row = s_rows[r];
            int idx = (row >= 0) ? nbr[(size_t)row * 27 + k] : -1;
            float4 val = make_float4(0.f, 0.f, 0.f, 0.f);
            if (idx >= 0) {
                val = *(const float4*)(in + (size_t)idx * CI + c4 * 4);
                int c = c4 * 4;
                val.x = fmaxf(fmaf(val.x, s_a[c + 0], s_b[c + 0]), 0.f);
                val.y = fmaxf(fmaf(val.y, s_a[c + 1], s_b[c + 1]), 0.f);
                val.z = fmaxf(fmaf(val.z, s_a[c + 2], s_b[c + 2]), 0.f);
                val.w = fmaxf(fmaf(val.w, s_a[c + 3], s_b[c + 3]), 0.f);
            }
            *(float4*)(s_x + r * CIP + c4 * 4) = val;
        }
        __syncthreads();

        if (!s_live[mysub][k]) continue;

#pragma unroll
        for (int c = 0; c < CI; ++c) {
            float xv = s_x[tid * CIP + c];
            acc[0] = fmaf(xv, s_w[c * COP + 0], acc[0]);
            acc[1] = fmaf(xv, s_w[c * COP + 1], acc[1]);
            acc[2] = fmaf(xv, s_w[c * COP + 2], acc[2]);
        }
    }

    int row = s_rows[tid];
#pragma unroll
    for (int j = 0; j < 3; ++j) {
        float y = (row >= 0) ? acc[j] : 0.f;
        atomicAdd(&s_stats[0][j], y);
        atomicAdd(&s_stats[1][j], y * y);
    }
    if (row >= 0) {
#pragma unroll
        for (int j = 0; j < 3; ++j) out[(size_t)row * 3 + j] = acc[j];
    }
    __syncthreads();
    if (tid < 3) {
        atomicAdd(&stats[tid], s_stats[0][tid]);
        atomicAdd(&stats[64 + tid], s_stats[1][tid]);
    }
}

extern "C" void kernel_launch(void* const* d_in, const int* in_sizes, int n_in,
                              void* d_out, int out_size) {
    const int* nbr4  = (const int*)d_in[0];
    const int* inv43 = (const int*)d_in[1];
    const int* nbr3  = (const int*)d_in[2];
    const int* inv32 = (const int*)d_in[3];
    const int* nbr2  = (const int*)d_in[4];
    const int* inv21 = (const int*)d_in[5];
    const int* nbr1  = (const int*)d_in[6];
    const float* x   = (const float*)d_in[7];

    const float* W_m4 = (const float*)d_in[8];
    const float* g_m4 = (const float*)d_in[9];
    const float* b_m4 = (const float*)d_in[10];
    const float* W_i4 = (const float*)d_in[11];
    const float* g_i4 = (const float*)d_in[12];
    const float* b_i4 = (const float*)d_in[13];
    const float* W_m3 = (const float*)d_in[14];
    const float* g_m3 = (const float*)d_in[15];
    const float* b_m3 = (const float*)d_in[16];
    const float* W_i3 = (const float*)d_in[17];
    const float* g_i3 = (const float*)d_in[18];
    const float* b_i3 = (const float*)d_in[19];
    const float* W_m2 = (const float*)d_in[20];
    const float* g_m2 = (const float*)d_in[21];
    const float* b_m2 = (const float*)d_in[22];
    const float* W_i2 = (const float*)d_in[23];
    const float* g_i2 = (const float*)d_in[24];
    const float* b_i2 = (const float*)d_in[25];
    const float* W_m1 = (const float*)d_in[26];
    const float* g_m1 = (const float*)d_in[27];
    const float* b_m1 = (const float*)d_in[28];
    const float* W_c5 = (const float*)d_in[29];
    const float* g_c5 = (const float*)d_in[30];
    const float* b_c5 = (const float*)d_in[31];

    const int n4 = in_sizes[0] / 27;
    const int n3 = in_sizes[1] / 27;
    const int n2 = in_sizes[3] / 27;
    const int n1 = in_sizes[5] / 27;

    float *bufA, *bufB, *stats, *aff;
    int* perm;
    cudaGetSymbolAddress((void**)&bufA, g_bufA);
    cudaGetSymbolAddress((void**)&bufB, g_bufB);
    cudaGetSymbolAddress((void**)&stats, g_stats);
    cudaGetSymbolAddress((void**)&aff, g_aff);
    cudaGetSymbolAddress((void**)&perm, g_perm);

    // smem sizes: TN*(CI+4)*4 + CI*CO*4
    constexpr int SM_L123 = (128 * 68 + 64 * 64) * 4;   // TN=128
    constexpr int SM_L4   = (128 * 68 + 64 * 32) * 4;   // TN=128
    constexpr int SM_L5   = (128 * 36 + 32 * 32) * 4;   // TN=128
    constexpr int SM_L6   = (256 * 36 + 32 * 16) * 4;   // TN=256
    constexpr int SM_L7   = (256 * 20 + 16 * 16) * 4;   // TN=256

    cudaFuncSetAttribute(gemm2_kernel<64, 64, 256, 4, 2, false>,
                         cudaFuncAttributeMaxDynamicSharedMemorySize, SM_L123);
    cudaFuncSetAttribute(gemm2_kernel<64, 64, 256, 4, 2, true>,
                         cudaFuncAttributeMaxDynamicSharedMemorySize, SM_L123);
    cudaFuncSetAttribute(gemm2_kernel<64, 32, 128, 4, 4, true>,
                         cudaFuncAttributeMaxDynamicSharedMemorySize, SM_L4);
    cudaFuncSetAttribute(gemm2_kernel<32, 32, 128, 4, 4, true>,
                         cudaFuncAttributeMaxDynamicSharedMemorySize, SM_L5);
    cudaFuncSetAttribute(gemm2_kernel<32, 16, 128, 4, 4, true>,
                         cudaFuncAttributeMaxDynamicSharedMemorySize, SM_L6);
    cudaFuncSetAttribute(gemm2_kernel<16, 16, 128, 4, 4, true>,
                         cudaFuncAttributeMaxDynamicSharedMemorySize, SM_L7);

    // ---- fused perm build (all 7 layers in 4 launches) ----
    PermArgs pa;
    pa.tab[0] = nbr4;  pa.n[0] = n4;
    pa.tab[1] = inv43; pa.n[1] = n3;
    pa.tab[2] = nbr3;  pa.n[2] = n3;
    pa.tab[3] = inv32; pa.n[3] = n2;
    pa.tab[4] = nbr2;  pa.n[4] = n2;
    pa.tab[5] = inv21; pa.n[5] = n1;
    pa.tab[6] = nbr1;  pa.n[6] = n1;
    pa.cum[0] = 0;
    for (int l = 0; l < 7; ++l)
        pa.cum[l + 1] = pa.cum[l] + (pa.n[l] + 255) / 256;
    int nblk = pa.cum[7];

    zero_hist_all_kernel<<<(7 * NB + 255) / 256, 256>>>();   // #0
    mask_hist_all_kernel<<<nblk, 256>>>(pa);                  // #1
    scan_all_kernel<<<7, NB>>>();                             // #2
    scatter_all_kernel<<<nblk, 256>>>(pa);                    // #3
    zero_stats_kernel<<<4, 256>>>();                          // #4

    // L1: m4 (x -> A), 64->64, N=n4   (launch #5 -> captured by ncu)
    gemm2_kernel<64, 64, 256, 4, 2, false><<<(n4 + 127) / 128, 256, SM_L123>>>(
        x, nbr4, W_m4, perm + 0 * MAXROWS, nullptr, bufA, stats + 0 * 128, n4);
    finalize_kernel<<<1, 64>>>(stats + 0 * 128, g_m4, b_m4, aff + 0 * 128, n4, 64);

    // L2: i4 (A -> B), 64->64, N=n3
    gemm2_kernel<64, 64, 256, 4, 2, true><<<(n3 + 127) / 128, 256, SM_L123>>>(
        bufA, inv43, W_i4, perm + 1 * MAXROWS, aff + 0 * 128, bufB,
        stats + 1 * 128, n3);
    finalize_kernel<<<1, 64>>>(stats + 1 * 128, g_i4, b_i4, aff + 1 * 128, n3, 64);

    // L3: m3 (B -> A), 64->64, N=n3
    gemm2_kernel<64, 64, 256, 4, 2, true><<<(n3 + 127) / 128, 256, SM_L123>>>(
        bufB, nbr3, W_m3, perm + 2 * MAXROWS, aff + 1 * 128, bufA,
        stats + 2 * 128, n3);
    finalize_kernel<<<1, 64>>>(stats + 2 * 128, g_m3, b_m3, aff + 2 * 128, n3, 64);

    // L4: i3 (A -> B), 64->32, N=n2
    gemm2_kernel<64, 32, 128, 4, 4, true><<<(n2 + 127) / 128, 128, SM_L4>>>(
        bufA, inv32, W_i3, perm + 3 * MAXROWS, aff + 2 * 128, bufB,
        stats + 3 * 128, n2);
    finalize_kernel<<<1, 64>>>(stats + 3 * 128, g_i3, b_i3, aff + 3 * 128, n2, 32);

    // L5: m2 (B -> A), 32->32, N=n2
    gemm2_kernel<32, 32, 128, 4, 4, true><<<(n2 + 127) / 128, 128, SM_L5>>>(
        bufB, nbr2, W_m2, perm + 4 * MAXROWS, aff + 3 * 128, bufA,
        stats + 4 * 128, n2);
    finalize_kernel<<<1, 64>>>(stats + 4 * 128, g_m2, b_m2, aff + 4 * 128, n2, 32);

    // L6: i2 (A -> B), 32->16, N=n1
    gemm2_kernel<32, 16, 128, 4, 4, true><<<(n1 + 255) / 256, 128, SM_L6>>>(
        bufA, inv21, W_i2, perm + 5 * MAXROWS, aff + 4 * 128, bufB,
        stats + 5 * 128, n1);
    finalize_kernel<<<1, 64>>>(stats + 5 * 128, g_i2, b_i2, aff + 5 * 128, n1, 16);

    // L7: m1 (B -> A), 16->16, N=n1
    gemm2_kernel<16, 16, 128, 4, 4, true><<<(n1 + 255) / 256, 128, SM_L7>>>(
        bufB, nbr1, W_m1, perm + 6 * MAXROWS, aff + 5 * 128, bufA,
        stats + 6 * 128, n1);
    finalize_kernel<<<1, 64>>>(stats + 6 * 128, g_m1, b_m1, aff + 6 * 128, n1, 16);

    // L8: c5 (A -> B raw), 16->3, perm-sorted + per-warp skip, applies aff6
    gemm_c5_kernel<<<(n1 + 255) / 256, 256>>>(
        bufA, nbr1, W_c5, perm + 6 * MAXROWS, aff + 6 * 128, bufB,
        stats + 7 * 128, n1);

    // final normalize (no relu)
    out_kernel<<<256, 256>>>(bufB, stats + 7 * 128, g_c5, b_c5,
                             (float*)d_out, n1);
}

// round 10
// speedup vs baseline: 1.7130x; 1.2132x over previous
#include <cuda_runtime.h>
#include <math.h>

// ---------------------------------------------------------------------------
// VoxelBackBone8x decoder: 8 x (gather-GEMM over 27 taps + BN + relu)
// R9: warp-private tap loops (no block syncs / no weight staging in mainloop;
//     weights read from global via L1; 16-row tap-skip granularity), on top of
//     R7/R8's mask-sorted permutation + lazy BN + f32x2 FFMA2 engine.
// ---------------------------------------------------------------------------

#define MAXROWS 102400
#define NB 1024

__device__ float g_bufA[MAXROWS * 64];
__device__ float g_bufB[MAXROWS * 64];
__device__ float g_stats[8 * 2 * 64];   // per layer: [sum(64), sumsq(64)]
__device__ float g_aff[8 * 2 * 64];     // per layer: [a(64), b(64)]
__device__ int      g_perm[7][MAXROWS];
__device__ unsigned g_keys[7][MAXROWS];
__device__ unsigned g_hist[7 * NB];
__device__ unsigned g_offs[7 * NB];
__device__ unsigned g_cnt[7 * NB];

struct PermArgs {
    const int* tab[7];
    int n[7];
    int cum[8];   // cumulative block counts (256-thread blocks)
};

// zeroes hist + cnt + stats in one launch
__global__ void zero_all_kernel() {
    int t = blockIdx.x * blockDim.x + threadIdx.x;
    if (t < 7 * NB) { g_hist[t] = 0u; g_cnt[t] = 0u; }
    if (t < 8 * 2 * 64) g_stats[t] = 0.f;
}

// ---------------------------------------------------------------------------
// Fused permutation build over all 7 layers.
// ---------------------------------------------------------------------------
__global__ void mask_hist_all_kernel(PermArgs pa) {
    __shared__ unsigned sh[NB];
    __shared__ int s_l;
    for (int i = threadIdx.x; i < NB; i += blockDim.x) sh[i] = 0;
    if (threadIdx.x == 0) {
        int l = 0;
        while (blockIdx.x >= (unsigned)pa.cum[l + 1]) ++l;
        s_l = l;
    }
    __syncthreads();
    int l = s_l;
    int i = (blockIdx.x - pa.cum[l]) * 256 + threadIdx.x;
    if (i < pa.n[l]) {
        const int* row = pa.tab[l] + (size_t)i * 27;
        unsigned m = 0;
#pragma unroll
        for (int k = 0; k < 27; ++k) m |= (row[k] >= 0 ? 1u : 0u) << k;
        unsigned key = (m * 2654435761u) >> 22;   // 10 bits
        g_keys[l][i] = key;
        atomicAdd(&sh[key], 1u);
    }
    __syncthreads();
    for (int j = threadIdx.x; j < NB; j += blockDim.x)
        if (sh[j]) atomicAdd(&g_hist[l * NB + j], sh[j]);
}

__global__ void scan_all_kernel() {   // grid = 7, block = NB
    __shared__ unsigned s[NB];
    int l = blockIdx.x;
    int t = threadIdx.x;
    unsigned h = g_hist[l * NB + t];
    s[t] = h;
    __syncthreads();
    for (int d = 1; d < NB; d <<= 1) {
        unsigned v = (t >= d) ? s[t - d] : 0;
        __syncthreads();
        s[t] += v;
        __syncthreads();
    }
    g_offs[l * NB + t] = s[t] - h;   // exclusive prefix
}

__global__ void scatter_all_kernel(PermArgs pa) {
    __shared__ unsigned bcnt[NB];
    __shared__ unsigned bbase[NB];
    __shared__ int s_l;
    for (int i = threadIdx.x; i < NB; i += blockDim.x) bcnt[i] = 0;
    if (threadIdx.x == 0) {
        int l = 0;
        while (blockIdx.x >= (unsigned)pa.cum[l + 1]) ++l;
        s_l = l;
    }
    __syncthreads();
    int l = s_l;
    int i = (blockIdx.x - pa.cum[l]) * 256 + threadIdx.x;
    unsigned key = 0, rank = 0;
    bool valid = (i < pa.n[l]);
    if (valid) { key = g_keys[l][i]; rank = atomicAdd(&bcnt[key], 1u); }
    __syncthreads();
    for (int j = threadIdx.x; j < NB; j += blockDim.x)
        if (bcnt[j]) bbase[j] = atomicAdd(&g_cnt[l * NB + j], bcnt[j]);
    __syncthreads();
    if (valid) g_perm[l][g_offs[l * NB + key] + bbase[key] + rank] = i;
}

// ---------------------------------------------------------------------------
// f32x2 helpers
// ---------------------------------------------------------------------------
__device__ __forceinline__ void ffma2(unsigned long long& d, unsigned long long a,
                                      unsigned long long b) {
    asm("fma.rn.f32x2 %0, %1, %2, %0;" : "+l"(d) : "l"(a), "l"(b));
}
__device__ __forceinline__ unsigned long long packf2(float x) {
    unsigned long long r;
    unsigned int u = __float_as_uint(x);
    asm("mov.b64 %0, {%1, %1};" : "=l"(r) : "r"(u));
    return r;
}
__device__ __forceinline__ float2 unpackf2(unsigned long long v) {
    float2 f;
    asm("mov.b64 {%0, %1}, %2;" : "=f"(f.x), "=f"(f.y) : "l"(v));
    return f;
}

// ---------------------------------------------------------------------------
// finalize: stats -> affine (a, b) for one layer
// ---------------------------------------------------------------------------
__global__ void finalize_kernel(const float* __restrict__ stats,
                                const float* __restrict__ g,
                                const float* __restrict__ b,
                                float* __restrict__ aff, int N, int CO) {
    int c = threadIdx.x;
    if (c < CO) {
        float invN = 1.0f / (float)N;
        float mu = stats[c] * invN;
        float var = stats[64 + c] * invN - mu * mu;
        float a = g[c] * rsqrtf(var + 1e-3f);
        aff[c] = a;
        aff[64 + c] = b[c] - mu * a;
    }
}

// final layer: out[n,3] = y[n,3]*a + b (no relu), affine from stats
__global__ void out_kernel(const float* __restrict__ y, const float* __restrict__ stats,
                           const float* __restrict__ g, const float* __restrict__ b,
                           float* __restrict__ out, int N) {
    __shared__ float sa[3], sb[3];
    int c = threadIdx.x;
    if (c < 3) {
        float invN = 1.0f / (float)N;
        float mu = stats[c] * invN;
        float var = stats[64 + c] * invN - mu * mu;
        float a = g[c] * rsqrtf(var + 1e-3f);
        sa[c] = a;
        sb[c] = b[c] - mu * a;
    }
    __syncthreads();
    int total = N * 3;
    for (int i = blockIdx.x * blockDim.x + threadIdx.x; i < total;
         i += gridDim.x * blockDim.x) {
        int j = i % 3;
        out[i] = fmaf(y[i], sa[j], sb[j]);
    }
}

// ---------------------------------------------------------------------------
// gemm3: warp-private gather-GEMM over mask-sorted rows.
//   NT threads; thread tile = RPT rows x 8 cols (split {4cg, H+4cg}).
//   Warp owns WR = (32/G)*RPT rows and its own s_x slice; iterates ONLY its
//   live taps (warp-reduced bitmask); weights read from global (L1-cached);
//   no block syncs in the main loop (warp-synchronous s_x).
// ---------------------------------------------------------------------------
template <int CI, int CO, int NT, int RPT, int MB, bool APPLY>
__launch_bounds__(NT, MB)
__global__ void gemm3_kernel(const float* __restrict__ in,
                             const int* __restrict__ nbr,
                             const float* __restrict__ W,   // [27][CI][CO]
                             const int* __restrict__ perm,  // [N] sorted rows
                             const float* __restrict__ aff, // [a(64), b(64)]
                             float* __restrict__ out,       // [N][CO] raw
                             float* __restrict__ stats,     // [sum(64), sumsq(64)]
                             int N) {
    constexpr int G = CO / 8;
    constexpr int ROWG = NT / G;
    constexpr int TN = ROWG * RPT;
    constexpr int CIP = CI + 4;
    constexpr int WR = (32 / G) * RPT;   // rows owned by one warp
    constexpr int C4 = CI / 4;
    constexpr int H = CO / 2;

    extern __shared__ float s_x[];       // TN * CIP

    __shared__ int s_rows[TN];
    __shared__ int s_nbr[TN * 27];
    __shared__ float s_stats[2][CO];
    __shared__ float s_a[CI], s_b[CI];

    const int tid = threadIdx.x;
    const int lane = tid & 31;
    const int warp = tid >> 5;
    const int rowbase = blockIdx.x * TN;

    if (tid < CO) { s_stats[0][tid] = 0.f; s_stats[1][tid] = 0.f; }
    if (APPLY) {
        for (int c = tid; c < CI; c += NT) {
            s_a[c] = aff[c];
            s_b[c] = aff[64 + c];
        }
    }
    for (int i = tid; i < TN; i += NT) {
        int gr = rowbase + i;
        s_rows[i] = (gr < N) ? perm[gr] : -1;
    }
    __syncthreads();
    // stage neighbor rows for the tile
    for (int i = tid; i < TN * 27; i += NT) {
        int r = i / 27;
        int k = i - r * 27;
        int row = s_rows[r];
        s_nbr[i] = (row >= 0) ? nbr[(size_t)row * 27 + k] : -1;
    }
    __syncthreads();

    const int cg = tid % G;
    const int rg = tid / G;
    const int r0 = rg * RPT;
    const int wbase = warp * WR;         // first row owned by this warp

    // warp-live tap mask (union over this warp's WR rows)
    unsigned m = 0;
    for (int i = lane; i < WR * 27; i += 32) {
        int r = wbase + i / 27;
        int k = i - (i / 27) * 27;
        if (s_nbr[r * 27 + k] >= 0) m |= 1u << k;
    }
    m = __reduce_or_sync(0xffffffffu, m);

    unsigned long long acc[RPT][4];
#pragma unroll
    for (int i = 0; i < RPT; ++i)
#pragma unroll
        for (int j = 0; j < 4; ++j) acc[i][j] = 0ULL;

    while (m) {
        const int k = __ffs(m) - 1;
        m &= m - 1;

        // warp-private gather of WR rows (apply prev BN+relu in flight)
        for (int i = lane; i < WR * C4; i += 32) {
            int rl = i / C4;
            int c4 = i - rl * C4;
            int r = wbase + rl;
            int idx = s_nbr[r * 27 + k];
            float4 val = make_float4(0.f, 0.f, 0.f, 0.f);
            if (idx >= 0) {
                val = *(const float4*)(in + (size_t)idx * CI + c4 * 4);
                if (APPLY) {
                    int c = c4 * 4;
                    val.x = fmaxf(fmaf(val.x, s_a[c + 0], s_b[c + 0]), 0.f);
                    val.y = fmaxf(fmaf(val.y, s_a[c + 1], s_b[c + 1]), 0.f);
                    val.z = fmaxf(fmaf(val.z, s_a[c + 2], s_b[c + 2]), 0.f);
                    val.w = fmaxf(fmaf(val.w, s_a[c + 3], s_b[c + 3]), 0.f);
                }
            }
            *(float4*)(s_x + r * CIP + c4 * 4) = val;
        }
        __syncwarp();

        // compute: weights straight from global (L1-resident per tap)
        const ulonglong2* __restrict__ Wk =
            (const ulonglong2*)(W + (size_t)k * CI * CO);
#pragma unroll 2
        for (int c = 0; c < CI; c += 2) {
            ulonglong2 wa0 = Wk[(c * CO + 4 * cg) >> 2];
            ulonglong2 wa1 = Wk[(c * CO + H + 4 * cg) >> 2];
            ulonglong2 wb0 = Wk[((c + 1) * CO + 4 * cg) >> 2];
            ulonglong2 wb1 = Wk[((c + 1) * CO + H + 4 * cg) >> 2];
#pragma unroll
            for (int i = 0; i < RPT; ++i) {
                float2 xv = *(const float2*)(s_x + (r0 + i) * CIP + c);
                unsigned long long xa = packf2(xv.x);
                unsigned long long xb = packf2(xv.y);
                ffma2(acc[i][0], xa, wa0.x);
                ffma2(acc[i][1], xa, wa0.y);
                ffma2(acc[i][2], xa, wa1.x);
                ffma2(acc[i][3], xa, wa1.y);
                ffma2(acc[i][0], xb, wb0.x);
                ffma2(acc[i][1], xb, wb0.y);
                ffma2(acc[i][2], xb, wb1.x);
                ffma2(acc[i][3], xb, wb1.y);
            }
        }
        __syncwarp();   // all lanes done reading s_x before next gather
    }

    // epilogue: store raw y + accumulate stats
#pragma unroll
    for (int j = 0; j < 4; ++j) {
        float s1 = 0.f, s2 = 0.f, t1 = 0.f, t2 = 0.f;
#pragma unroll
        for (int i = 0; i < RPT; ++i) {
            if (s_rows[r0 + i] >= 0) {
                float2 p = unpackf2(acc[i][j]);
                s1 += p.x; s2 += p.x * p.x;
                t1 += p.y; t2 += p.y * p.y;
            }
        }
        int base = (j < 2) ? (4 * cg + 2 * j) : (H + 4 * cg + 2 * (j - 2));
        atomicAdd(&s_stats[0][base + 0], s1);
        atomicAdd(&s_stats[1][base + 0], s2);
        atomicAdd(&s_stats[0][base + 1], t1);
        atomicAdd(&s_stats[1][base + 1], t2);
    }
#pragma unroll
    for (int i = 0; i < RPT; ++i) {
        int row = s_rows[r0 + i];
        if (row >= 0) {
            float2 p0 = unpackf2(acc[i][0]);
            float2 p1 = unpackf2(acc[i][1]);
            float2 p2 = unpackf2(acc[i][2]);
            float2 p3 = unpackf2(acc[i][3]);
            *(float4*)(out + (size_t)row * CO + 4 * cg) =
                make_float4(p0.x, p0.y, p1.x, p1.y);
            *(float4*)(out + (size_t)row * CO + H + 4 * cg) =
                make_float4(p2.x, p2.y, p3.x, p3.y);
        }
    }
    __syncthreads();
    if (tid < CO) {
        atomicAdd(&stats[tid], s_stats[0][tid]);
        atomicAdd(&stats[64 + tid], s_stats[1][tid]);
    }
}

// ---------------------------------------------------------------------------
// Final 16->3 conv: one row per lane, fully register-resident, warp-private
// tap loop (no syncs in mainloop), weights broadcast-read from global.
// ---------------------------------------------------------------------------
__launch_bounds__(256, 4)
__global__ void gemm_c5_kernel(const float* __restrict__ in,
                               const int* __restrict__ nbr,
                               const float* __restrict__ W,     // [27][16][3]
                               const int* __restrict__ perm,
                               const float* __restrict__ aff,   // layer-7 affine
                               float* __restrict__ out,         // [N][3] raw
                               float* __restrict__ stats,
                               int N) {
    constexpr int CI = 16, TN = 256;

    __shared__ int s_rows[TN];
    __shared__ int s_nbr[TN * 27];
    __shared__ float s_a[CI], s_b[CI];
    __shared__ float s_stats[2][4];

    const int tid = threadIdx.x;
    const int lane = tid & 31;
    const int rowbase = blockIdx.x * TN;

    if (tid < 4) { s_stats[0][tid] = 0.f; s_stats[1][tid] = 0.f; }
    if (tid < CI) { s_a[tid] = aff[tid]; s_b[tid] = aff[64 + tid]; }
    {
        int gr = rowbase + tid;
        s_rows[tid] = (gr < N) ? perm[gr] : -1;
    }
    __syncthreads();
    for (int i = tid; i < TN * 27; i += 256) {
        int r = i / 27;
        int row = s_rows[r];
        s_nbr[i] = (row >= 0) ? nbr[(size_t)row * 27 + (i - r * 27)] : -1;
    }
    __syncthreads();

    // per-lane (= per-row) mask, warp union for uniform loop
    unsigned m = 0;
#pragma unroll
    for (int k = 0; k < 27; ++k)
        if (s_nbr[tid * 27 + k] >= 0) m |= 1u << k;
    unsigned wm = __reduce_or_sync(0xffffffffu, m);

    float acc[3] = {0.f, 0.f, 0.f};

    while (wm) {
        const int k = __ffs(wm) - 1;
        wm &= wm - 1;
        int idx = s_nbr[tid * 27 + k];
        if (idx >= 0) {
            const float* xr = in + (size_t)idx * CI;
            const float* wk = W + (size_t)k * CI * 3;
#pragma unroll
            for (int c4 = 0; c4 < 4; ++c4) {
                float4 v = *(const float4*)(xr + c4 * 4);
                int c = c4 * 4;
                v.x = fmaxf(fmaf(v.x, s_a[c + 0], s_b[c + 0]), 0.f);
                v.y = fmaxf(fmaf(v.y, s_a[c + 1], s_b[c + 1]), 0.f);
                v.z = fmaxf(fmaf(v.z, s_a[c + 2], s_b[c + 2]), 0.f);
                v.w = fmaxf(fmaf(v.w, s_a[c + 3], s_b[c + 3]), 0.f);
                float xs[4] = {v.x, v.y, v.z, v.w};
#pragma unroll
                for (int u = 0; u < 4; ++u) {
                    acc[0] = fmaf(xs[u], __ldg(wk + (c + u) * 3 + 0), acc[0]);
                    acc[1] = fmaf(xs[u], __ldg(wk + (c + u) * 3 + 1), acc[1]);
                    acc[2] = fmaf(xs[u], __ldg(wk + (c + u) * 3 + 2), acc[2]);
                }
            }
        }
    }
    (void)lane;

    int row = s_rows[tid];
#pragma unroll
    for (int j = 0; j < 3; ++j) {
        float y = (row >= 0) ? acc[j] : 0.f;
        atomicAdd(&s_stats[0][j], y);
        atomicAdd(&s_stats[1][j], y * y);
    }
    if (row >= 0) {
#pragma unroll
        for (int j = 0; j < 3; ++j) out[(size_t)row * 3 + j] = acc[j];
    }
    __syncthreads();
    if (tid < 3) {
        atomicAdd(&stats[tid], s_stats[0][tid]);
        atomicAdd(&stats[64 + tid], s_stats[1][tid]);
    }
}

extern "C" void kernel_launch(void* const* d_in, const int* in_sizes, int n_in,
                              void* d_out, int out_size) {
    const int* nbr4  = (const int*)d_in[0];
    const int* inv43 = (const int*)d_in[1];
    const int* nbr3  = (const int*)d_in[2];
    const int* inv32 = (const int*)d_in[3];
    const int* nbr2  = (const int*)d_in[4];
    const int* inv21 = (const int*)d_in[5];
    const int* nbr1  = (const int*)d_in[6];
    const float* x   = (const float*)d_in[7];

    const float* W_m4 = (const float*)d_in[8];
    const float* g_m4 = (const float*)d_in[9];
    const float* b_m4 = (const float*)d_in[10];
    const float* W_i4 = (const float*)d_in[11];
    const float* g_i4 = (const float*)d_in[12];
    const float* b_i4 = (const float*)d_in[13];
    const float* W_m3 = (const float*)d_in[14];
    const float* g_m3 = (const float*)d_in[15];
    const float* b_m3 = (const float*)d_in[16];
    const float* W_i3 = (const float*)d_in[17];
    const float* g_i3 = (const float*)d_in[18];
    const float* b_i3 = (const float*)d_in[19];
    const float* W_m2 = (const float*)d_in[20];
    const float* g_m2 = (const float*)d_in[21];
    const float* b_m2 = (const float*)d_in[22];
    const float* W_i2 = (const float*)d_in[23];
    const float* g_i2 = (const float*)d_in[24];
    const float* b_i2 = (const float*)d_in[25];
    const float* W_m1 = (const float*)d_in[26];
    const float* g_m1 = (const float*)d_in[27];
    const float* b_m1 = (const float*)d_in[28];
    const float* W_c5 = (const float*)d_in[29];
    const float* g_c5 = (const float*)d_in[30];
    const float* b_c5 = (const float*)d_in[31];

    const int n4 = in_sizes[0] / 27;
    const int n3 = in_sizes[1] / 27;
    const int n2 = in_sizes[3] / 27;
    const int n1 = in_sizes[5] / 27;

    float *bufA, *bufB, *stats, *aff;
    int* perm;
    cudaGetSymbolAddress((void**)&bufA, g_bufA);
    cudaGetSymbolAddress((void**)&bufB, g_bufB);
    cudaGetSymbolAddress((void**)&stats, g_stats);
    cudaGetSymbolAddress((void**)&aff, g_aff);
    cudaGetSymbolAddress((void**)&perm, g_perm);

    // dynamic smem = TN * (CI+4) * 4
    constexpr int SM_CI64 = 128 * 68 * 4;   // 34816
    constexpr int SM_CI32 = 128 * 36 * 4;   // 18432
    constexpr int SM_CI16 = 128 * 20 * 4;   // 10240

    cudaFuncSetAttribute(gemm3_kernel<64, 64, 256, 4, 2, false>,
                         cudaFuncAttributeMaxDynamicSharedMemorySize, SM_CI64);
    cudaFuncSetAttribute(gemm3_kernel<64, 64, 256, 4, 2, true>,
                         cudaFuncAttributeMaxDynamicSharedMemorySize, SM_CI64);
    cudaFuncSetAttribute(gemm3_kernel<64, 32, 128, 4, 4, true>,
                         cudaFuncAttributeMaxDynamicSharedMemorySize, SM_CI64);
    cudaFuncSetAttribute(gemm3_kernel<32, 32, 128, 4, 4, true>,
                         cudaFuncAttributeMaxDynamicSharedMemorySize, SM_CI32);
    cudaFuncSetAttribute(gemm3_kernel<32, 16, 128, 2, 4, true>,
                         cudaFuncAttributeMaxDynamicSharedMemorySize, SM_CI32);
    cudaFuncSetAttribute(gemm3_kernel<16, 16, 128, 2, 4, true>,
                         cudaFuncAttributeMaxDynamicSharedMemorySize, SM_CI16);

    // ---- fused perm build (all 7 layers) ----
    PermArgs pa;
    pa.tab[0] = nbr4;  pa.n[0] = n4;
    pa.tab[1] = inv43; pa.n[1] = n3;
    pa.tab[2] = nbr3;  pa.n[2] = n3;
    pa.tab[3] = inv32; pa.n[3] = n2;
    pa.tab[4] = nbr2;  pa.n[4] = n2;
    pa.tab[5] = inv21; pa.n[5] = n1;
    pa.tab[6] = nbr1;  pa.n[6] = n1;
    pa.cum[0] = 0;
    for (int l = 0; l < 7; ++l)
        pa.cum[l + 1] = pa.cum[l] + (pa.n[l] + 255) / 256;
    int nblk = pa.cum[7];

    zero_all_kernel<<<(7 * NB + 255) / 256, 256>>>();
    mask_hist_all_kernel<<<nblk, 256>>>(pa);
    scan_all_kernel<<<7, NB>>>();
    scatter_all_kernel<<<nblk, 256>>>(pa);

    // L1: m4 (x -> A), 64->64, N=n4
    gemm3_kernel<64, 64, 256, 4, 2, false><<<(n4 + 127) / 128, 256, SM_CI64>>>(
        x, nbr4, W_m4, perm + 0 * MAXROWS, nullptr, bufA, stats + 0 * 128, n4);
    finalize_kernel<<<1, 64>>>(stats + 0 * 128, g_m4, b_m4, aff + 0 * 128, n4, 64);

    // L2: i4 (A -> B), 64->64, N=n3
    gemm3_kernel<64, 64, 256, 4, 2, true><<<(n3 + 127) / 128, 256, SM_CI64>>>(
        bufA, inv43, W_i4, perm + 1 * MAXROWS, aff + 0 * 128, bufB,
        stats + 1 * 128, n3);
    finalize_kernel<<<1, 64>>>(stats + 1 * 128, g_i4, b_i4, aff + 1 * 128, n3, 64);

    // L3: m3 (B -> A), 64->64, N=n3
    gemm3_kernel<64, 64, 256, 4, 2, true><<<(n3 + 127) / 128, 256, SM_CI64>>>(
        bufB, nbr3, W_m3, perm + 2 * MAXROWS, aff + 1 * 128, bufA,
        stats + 2 * 128, n3);
    finalize_kernel<<<1, 64>>>(stats + 2 * 128, g_m3, b_m3, aff + 2 * 128, n3, 64);

    // L4: i3 (A -> B), 64->32, N=n2
    gemm3_kernel<64, 32, 128, 4, 4, true><<<(n2 + 127) / 128, 128, SM_CI64>>>(
        bufA, inv32, W_i3, perm + 3 * MAXROWS, aff + 2 * 128, bufB,
        stats + 3 * 128, n2);
    finalize_kernel<<<1, 64>>>(stats + 3 * 128, g_i3, b_i3, aff + 3 * 128, n2, 32);

    // L5: m2 (B -> A), 32->32, N=n2
    gemm3_kernel<32, 32, 128, 4, 4, true><<<(n2 + 127) / 128, 128, SM_CI32>>>(
        bufB, nbr2, W_m2, perm + 4 * MAXROWS, aff + 3 * 128, bufA,
        stats + 4 * 128, n2);
    finalize_kernel<<<1, 64>>>(stats + 4 * 128, g_m2, b_m2, aff + 4 * 128, n2, 32);

    // L6: i2 (A -> B), 32->16, N=n1
    gemm3_kernel<32, 16, 128, 2, 4, true><<<(n1 + 127) / 128, 128, SM_CI32>>>(
        bufA, inv21, W_i2, perm + 5 * MAXROWS, aff + 4 * 128, bufB,
        stats + 5 * 128, n1);
    finalize_kernel<<<1, 64>>>(stats + 5 * 128, g_i2, b_i2, aff + 5 * 128, n1, 16);

    // L7: m1 (B -> A), 16->16, N=n1
    gemm3_kernel<16, 16, 128, 2, 4, true><<<(n1 + 127) / 128, 128, SM_CI16>>>(
        bufB, nbr1, W_m1, perm + 6 * MAXROWS, aff + 5 * 128, bufA,
        stats + 6 * 128, n1);
    finalize_kernel<<<1, 64>>>(stats + 6 * 128, g_m1, b_m1, aff + 6 * 128, n1, 16);

    // L8: c5 (A -> B raw), 16->3, register-resident warp loop
    gemm_c5_kernel<<<(n1 + 255) / 256, 256>>>(
        bufA, nbr1, W_c5, perm + 6 * MAXROWS, aff + 6 * 128, bufB,
        stats + 7 * 128, n1);

    // final normalize (no relu)
    out_kernel<<<256, 256>>>(bufB, stats + 7 * 128, g_c5, b_c5,
                             (float*)d_out, n1);
}

// round 12
// speedup vs baseline: 1.7929x; 1.0467x over previous
#include <cuda_runtime.h>
#include <math.h>

// ---------------------------------------------------------------------------
// VoxelBackBone8x decoder: 8 x (gather-GEMM over 27 taps + BN + relu)
// R11 == R10 resubmission (R11 bench died in the broker, kernel never ran):
//      hybrid weight path (DENSE: block-staged smem weights for L1; sparse
//      layers keep R9 warp-private loops), finalize kernels fused into gemm
//      prologues, launch order puts the L1 gemm in the ncu capture slot.
// ---------------------------------------------------------------------------

#define MAXROWS 102400
#define NB 1024

__device__ float g_bufA[MAXROWS * 64];
__device__ float g_bufB[MAXROWS * 64];
__device__ float g_stats[8 * 2 * 64];   // per layer: [sum(64), sumsq(64)]
__device__ int      g_perm[7][MAXROWS];
__device__ unsigned g_keys[7][MAXROWS];
__device__ unsigned g_hist[7 * NB];
__device__ unsigned g_offs[7 * NB];
__device__ unsigned g_cnt[7 * NB];

struct PermArgs {
    const int* tab[7];
    int n[7];
    int cum[8];   // cumulative block counts (256-thread blocks)
};

// zeroes hist + cnt + stats in one launch
__global__ void zero_all_kernel() {
    int t = blockIdx.x * blockDim.x + threadIdx.x;
    if (t < 7 * NB) { g_hist[t] = 0u; g_cnt[t] = 0u; }
    if (t < 8 * 2 * 64) g_stats[t] = 0.f;
}

// ---------------------------------------------------------------------------
// Fused permutation build over all 7 layers.
// ---------------------------------------------------------------------------
__global__ void mask_hist_all_kernel(PermArgs pa) {
    __shared__ unsigned sh[NB];
    __shared__ int s_l;
    for (int i = threadIdx.x; i < NB; i += blockDim.x) sh[i] = 0;
    if (threadIdx.x == 0) {
        int l = 0;
        while (blockIdx.x >= (unsigned)pa.cum[l + 1]) ++l;
        s_l = l;
    }
    __syncthreads();
    int l = s_l;
    int i = (blockIdx.x - pa.cum[l]) * 256 + threadIdx.x;
    if (i < pa.n[l]) {
        const int* row = pa.tab[l] + (size_t)i * 27;
        unsigned m = 0;
#pragma unroll
        for (int k = 0; k < 27; ++k) m |= (row[k] >= 0 ? 1u : 0u) << k;
        unsigned key = (m * 2654435761u) >> 22;   // 10 bits
        g_keys[l][i] = key;
        atomicAdd(&sh[key], 1u);
    }
    __syncthreads();
    for (int j = threadIdx.x; j < NB; j += blockDim.x)
        if (sh[j]) atomicAdd(&g_hist[l * NB + j], sh[j]);
}

__global__ void scan_all_kernel() {   // grid = 7, block = NB
    __shared__ unsigned s[NB];
    int l = blockIdx.x;
    int t = threadIdx.x;
    unsigned h = g_hist[l * NB + t];
    s[t] = h;
    __syncthreads();
    for (int d = 1; d < NB; d <<= 1) {
        unsigned v = (t >= d) ? s[t - d] : 0;
        __syncthreads();
        s[t] += v;
        __syncthreads();
    }
    g_offs[l * NB + t] = s[t] - h;   // exclusive prefix
}

__global__ void scatter_all_kernel(PermArgs pa) {
    __shared__ unsigned bcnt[NB];
    __shared__ unsigned bbase[NB];
    __shared__ int s_l;
    for (int i = threadIdx.x; i < NB; i += blockDim.x) bcnt[i] = 0;
    if (threadIdx.x == 0) {
        int l = 0;
        while (blockIdx.x >= (unsigned)pa.cum[l + 1]) ++l;
        s_l = l;
    }
    __syncthreads();
    int l = s_l;
    int i = (blockIdx.x - pa.cum[l]) * 256 + threadIdx.x;
    unsigned key = 0, rank = 0;
    bool valid = (i < pa.n[l]);
    if (valid) { key = g_keys[l][i]; rank = atomicAdd(&bcnt[key], 1u); }
    __syncthreads();
    for (int j = threadIdx.x; j < NB; j += blockDim.x)
        if (bcnt[j]) bbase[j] = atomicAdd(&g_cnt[l * NB + j], bcnt[j]);
    __syncthreads();
    if (valid) g_perm[l][g_offs[l * NB + key] + bbase[key] + rank] = i;
}

// ---------------------------------------------------------------------------
// f32x2 helpers
// ---------------------------------------------------------------------------
__device__ __forceinline__ void ffma2(unsigned long long& d, unsigned long long a,
                                      unsigned long long b) {
    asm("fma.rn.f32x2 %0, %1, %2, %0;" : "+l"(d) : "l"(a), "l"(b));
}
__device__ __forceinline__ unsigned long long packf2(float x) {
    unsigned long long r;
    unsigned int u = __float_as_uint(x);
    asm("mov.b64 %0, {%1, %1};" : "=l"(r) : "r"(u));
    return r;
}
__device__ __forceinline__ float2 unpackf2(unsigned long long v) {
    float2 f;
    asm("mov.b64 {%0, %1}, %2;" : "=f"(f.x), "=f"(f.y) : "l"(v));
    return f;
}

// final layer: out[n,3] = y[n,3]*a + b (no relu), affine from stats
__global__ void out_kernel(const float* __restrict__ y, const float* __restrict__ stats,
                           const float* __restrict__ g, const float* __restrict__ b,
                           float* __restrict__ out, int N) {
    __shared__ float sa[3], sb[3];
    int c = threadIdx.x;
    if (c < 3) {
        float invN = 1.0f / (float)N;
        float mu = stats[c] * invN;
        float var = stats[64 + c] * invN - mu * mu;
        float a = g[c] * rsqrtf(var + 1e-3f);
        sa[c] = a;
        sb[c] = b[c] - mu * a;
    }
    __syncthreads();
    int total = N * 3;
    for (int i = blockIdx.x * blockDim.x + threadIdx.x; i < total;
         i += gridDim.x * blockDim.x) {
        int j = i % 3;
        out[i] = fmaf(y[i], sa[j], sb[j]);
    }
}

// ---------------------------------------------------------------------------
// gemm3: gather-GEMM over (optionally) mask-sorted rows.
//   NT threads; thread tile = RPT rows x 8 cols (split {4cg, H+4cg}).
//   Warp owns WR rows + its own s_x slice; iterates only its live taps.
//   DENSE: block-synchronous tap loop with smem-staged weights (for layers
//          where nearly all taps are live -> weight traffic per block).
//  !DENSE: warp-private tap loop, weights straight from global (L1/L2).
//   APPLY: previous layer's BN affine computed IN-BLOCK from its stats.
//   perm == nullptr -> identity row order.
// ---------------------------------------------------------------------------
template <int CI, int CO, int NT, int RPT, int MB, bool APPLY, bool DENSE>
__launch_bounds__(NT, MB)
__global__ void gemm3_kernel(const float* __restrict__ in,
                             const int* __restrict__ nbr,
                             const float* __restrict__ W,    // [27][CI][CO]
                             const int* __restrict__ perm,   // [N] or null
                             const float* __restrict__ pstat,// prev stats
                             const float* __restrict__ pg,   // prev gamma
                             const float* __restrict__ pb,   // prev beta
                             int prevN,
                             float* __restrict__ out,        // [N][CO] raw
                             float* __restrict__ stats,      // [sum, sumsq]
                             int N) {
    constexpr int G = CO / 8;
    constexpr int ROWG = NT / G;
    constexpr int TN = ROWG * RPT;
    constexpr int CIP = CI + 4;
    constexpr int WR = (32 / G) * RPT;   // rows owned by one warp
    constexpr int C4 = CI / 4;
    constexpr int H = CO / 2;

    extern __shared__ float s_x[];       // TN*CIP (+ CI*CO weights if DENSE)
    float* s_w = s_x + TN * CIP;

    __shared__ int s_rows[TN];
    __shared__ int s_nbr[TN * 27];
    __shared__ float s_stats[2][CO];
    __shared__ float s_a[CI], s_b[CI];

    const int tid = threadIdx.x;
    const int lane = tid & 31;
    const int warp = tid >> 5;
    const int rowbase = blockIdx.x * TN;

    if (tid < CO) { s_stats[0][tid] = 0.f; s_stats[1][tid] = 0.f; }
    if (APPLY) {
        for (int c = tid; c < CI; c += NT) {
            float invN = 1.0f / (float)prevN;
            float mu = pstat[c] * invN;
            float var = pstat[64 + c] * invN - mu * mu;
            float a = pg[c] * rsqrtf(var + 1e-3f);
            s_a[c] = a;
            s_b[c] = pb[c] - mu * a;
        }
    }
    for (int i = tid; i < TN; i += NT) {
        int gr = rowbase + i;
        s_rows[i] = (gr < N) ? (perm ? perm[gr] : gr) : -1;
    }
    __syncthreads();
    // stage neighbor rows for the tile
    for (int i = tid; i < TN * 27; i += NT) {
        int r = i / 27;
        int k = i - r * 27;
        int row = s_rows[r];
        s_nbr[i] = (row >= 0) ? nbr[(size_t)row * 27 + k] : -1;
    }
    __syncthreads();

    const int cg = tid % G;
    const int rg = tid / G;
    const int r0 = rg * RPT;
    const int wbase = warp * WR;         // first row owned by this warp

    // warp-live tap mask (union over this warp's WR rows)
    unsigned m = 0;
    for (int i = lane; i < WR * 27; i += 32) {
        int r = wbase + i / 27;
        int k = i - (i / 27) * 27;
        if (s_nbr[r * 27 + k] >= 0) m |= 1u << k;
    }
    m = __reduce_or_sync(0xffffffffu, m);

    unsigned long long acc[RPT][4];
#pragma unroll
    for (int i = 0; i < RPT; ++i)
#pragma unroll
        for (int j = 0; j < 4; ++j) acc[i][j] = 0ULL;

    // warp-private gather of WR rows for tap k (applies prev BN+relu)
    auto gather = [&](int k) {
        for (int i = lane; i < WR * C4; i += 32) {
            int rl = i / C4;
            int c4 = i - rl * C4;
            int r = wbase + rl;
            int idx = s_nbr[r * 27 + k];
            float4 val = make_float4(0.f, 0.f, 0.f, 0.f);
            if (idx >= 0) {
                val = *(const float4*)(in + (size_t)idx * CI + c4 * 4);
                if (APPLY) {
                    int c = c4 * 4;
                    val.x = fmaxf(fmaf(val.x, s_a[c + 0], s_b[c + 0]), 0.f);
                    val.y = fmaxf(fmaf(val.y, s_a[c + 1], s_b[c + 1]), 0.f);
                    val.z = fmaxf(fmaf(val.z, s_a[c + 2], s_b[c + 2]), 0.f);
                    val.w = fmaxf(fmaf(val.w, s_a[c + 3], s_b[c + 3]), 0.f);
                }
            }
            *(float4*)(s_x + r * CIP + c4 * 4) = val;
        }
    };

    // FFMA2 block over one tap, weights via 16B vectors at base Wk
    auto compute = [&](const ulonglong2* __restrict__ Wk) {
#pragma unroll 2
        for (int c = 0; c < CI; c += 2) {
            ulonglong2 wa0 = Wk[(c * CO + 4 * cg) >> 2];
            ulonglong2 wa1 = Wk[(c * CO + H + 4 * cg) >> 2];
            ulonglong2 wb0 = Wk[((c + 1) * CO + 4 * cg) >> 2];
            ulonglong2 wb1 = Wk[((c + 1) * CO + H + 4 * cg) >> 2];
#pragma unroll
            for (int i = 0; i < RPT; ++i) {
                float2 xv = *(const float2*)(s_x + (r0 + i) * CIP + c);
                unsigned long long xa = packf2(xv.x);
                unsigned long long xb = packf2(xv.y);
                ffma2(acc[i][0], xa, wa0.x);
                ffma2(acc[i][1], xa, wa0.y);
                ffma2(acc[i][2], xa, wa1.x);
                ffma2(acc[i][3], xa, wa1.y);
                ffma2(acc[i][0], xb, wb0.x);
                ffma2(acc[i][1], xb, wb0.y);
                ffma2(acc[i][2], xb, wb1.x);
                ffma2(acc[i][3], xb, wb1.y);
            }
        }
    };

    if (DENSE) {
        // block-synchronous loop, weights staged to smem once per tap
        for (int k = 0; k < 27; ++k) {
            __syncthreads();   // previous tap's s_w readers done
            const float4* Wk4 = (const float4*)(W + (size_t)k * CI * CO);
            for (int v = tid; v < CI * CO / 4; v += NT)
                ((float4*)s_w)[v] = Wk4[v];
            bool live = (m >> k) & 1u;
            if (live) gather(k);
            __syncthreads();   // s_w staged + s_x gathered
            if (live) compute((const ulonglong2*)s_w);
        }
    } else {
        // warp-private loop, weights straight from global (L1/L2 cached)
        unsigned mm = m;
        while (mm) {
            const int k = __ffs(mm) - 1;
            mm &= mm - 1;
            gather(k);
            __syncwarp();
            compute((const ulonglong2*)(W + (size_t)k * CI * CO));
            __syncwarp();   // all lanes done reading s_x before next gather
        }
    }

    // epilogue: store raw y + accumulate stats
#pragma unroll
    for (int j = 0; j < 4; ++j) {
        float s1 = 0.f, s2 = 0.f, t1 = 0.f, t2 = 0.f;
#pragma unroll
        for (int i = 0; i < RPT; ++i) {
            if (s_rows[r0 + i] >= 0) {
                float2 p = unpackf2(acc[i][j]);
                s1 += p.x; s2 += p.x * p.x;
                t1 += p.y; t2 += p.y * p.y;
            }
        }
        int base = (j < 2) ? (4 * cg + 2 * j) : (H + 4 * cg + 2 * (j - 2));
        atomicAdd(&s_stats[0][base + 0], s1);
        atomicAdd(&s_stats[1][base + 0], s2);
        atomicAdd(&s_stats[0][base + 1], t1);
        atomicAdd(&s_stats[1][base + 1], t2);
    }
#pragma unroll
    for (int i = 0; i < RPT; ++i) {
        int row = s_rows[r0 + i];
        if (row >= 0) {
            float2 p0 = unpackf2(acc[i][0]);
            float2 p1 = unpackf2(acc[i][1]);
            float2 p2 = unpackf2(acc[i][2]);
            float2 p3 = unpackf2(acc[i][3]);
            *(float4*)(out + (size_t)row * CO + 4 * cg) =
                make_float4(p0.x, p0.y, p1.x, p1.y);
            *(float4*)(out + (size_t)row * CO + H + 4 * cg) =
                make_float4(p2.x, p2.y, p3.x, p3.y);
        }
    }
    __syncthreads();
    if (tid < CO) {
        atomicAdd(&stats[tid], s_stats[0][tid]);
        atomicAdd(&stats[64 + tid], s_stats[1][tid]);
    }
}

// ---------------------------------------------------------------------------
// Final 16->3 conv: one row per lane, register-resident, warp-private tap
// loop; prev-layer affine computed in-block from stats.
// ---------------------------------------------------------------------------
__launch_bounds__(256, 4)
__global__ void gemm_c5_kernel(const float* __restrict__ in,
                               const int* __restrict__ nbr,
                               const float* __restrict__ W,     // [27][16][3]
                               const int* __restrict__ perm,
                               const float* __restrict__ pstat, // layer-7 stats
                               const float* __restrict__ pg,
                               const float* __restrict__ pb,
                               int prevN,
                               float* __restrict__ out,         // [N][3] raw
                               float* __restrict__ stats,
                               int N) {
    constexpr int CI = 16, TN = 256;

    __shared__ int s_rows[TN];
    __shared__ int s_nbr[TN * 27];
    __shared__ float s_a[CI], s_b[CI];
    __shared__ float s_stats[2][4];

    const int tid = threadIdx.x;
    const int rowbase = blockIdx.x * TN;

    if (tid < 4) { s_stats[0][tid] = 0.f; s_stats[1][tid] = 0.f; }
    if (tid < CI) {
        float invN = 1.0f / (float)prevN;
        float mu = pstat[tid] * invN;
        float var = pstat[64 + tid] * invN - mu * mu;
        float a = pg[tid] * rsqrtf(var + 1e-3f);
        s_a[tid] = a;
        s_b[tid] = pb[tid] - mu * a;
    }
    {
        int gr = rowbase + tid;
        s_rows[tid] = (gr < N) ? perm[gr] : -1;
    }
    __syncthreads();
    for (int i = tid; i < TN * 27; i += 256) {
        int r = i / 27;
        int row = s_rows[r];
        s_nbr[i] = (row >= 0) ? nbr[(size_t)row * 27 + (i - r * 27)] : -1;
    }
    __syncthreads();

    unsigned m = 0;
#pragma unroll
    for (int k = 0; k < 27; ++k)
        if (s_nbr[tid * 27 + k] >= 0) m |= 1u << k;
    unsigned wm = __reduce_or_sync(0xffffffffu, m);

    float acc[3] = {0.f, 0.f, 0.f};

    while (wm) {
        const int k = __ffs(wm) - 1;
        wm &= wm - 1;
        int idx = s_nbr[tid * 27 + k];
        if (idx >= 0) {
            const float* xr = in + (size_t)idx * CI;
            const float* wk = W + (size_t)k * CI * 3;
#pragma unroll
            for (int c4 = 0; c4 < 4; ++c4) {
                float4 v = *(const float4*)(xr + c4 * 4);
                int c = c4 * 4;
                v.x = fmaxf(fmaf(v.x, s_a[c + 0], s_b[c + 0]), 0.f);
                v.y = fmaxf(fmaf(v.y, s_a[c + 1], s_b[c + 1]), 0.f);
                v.z = fmaxf(fmaf(v.z, s_a[c + 2], s_b[c + 2]), 0.f);
                v.w = fmaxf(fmaf(v.w, s_a[c + 3], s_b[c + 3]), 0.f);
                float xs[4] = {v.x, v.y, v.z, v.w};
#pragma unroll
                for (int u = 0; u < 4; ++u) {
                    acc[0] = fmaf(xs[u], __ldg(wk + (c + u) * 3 + 0), acc[0]);
                    acc[1] = fmaf(xs[u], __ldg(wk + (c + u) * 3 + 1), acc[1]);
                    acc[2] = fmaf(xs[u], __ldg(wk + (c + u) * 3 + 2), acc[2]);
                }
            }
        }
    }

    int row = s_rows[tid];
#pragma unroll
    for (int j = 0; j < 3; ++j) {
        float y = (row >= 0) ? acc[j] : 0.f;
        atomicAdd(&s_stats[0][j], y);
        atomicAdd(&s_stats[1][j], y * y);
    }
    if (row >= 0) {
#pragma unroll
        for (int j = 0; j < 3; ++j) out[(size_t)row * 3 + j] = acc[j];
    }
    __syncthreads();
    if (tid < 3) {
        atomicAdd(&stats[tid], s_stats[0][tid]);
        atomicAdd(&stats[64 + tid], s_stats[1][tid]);
    }
}

extern "C" void kernel_launch(void* const* d_in, const int* in_sizes, int n_in,
                              void* d_out, int out_size) {
    const int* nbr4  = (const int*)d_in[0];
    const int* inv43 = (const int*)d_in[1];
    const int* nbr3  = (const int*)d_in[2];
    const int* inv32 = (const int*)d_in[3];
    const int* nbr2  = (const int*)d_in[4];
    const int* inv21 = (const int*)d_in[5];
    const int* nbr1  = (const int*)d_in[6];
    const float* x   = (const float*)d_in[7];

    const float* W_m4 = (const float*)d_in[8];
    const float* g_m4 = (const float*)d_in[9];
    const float* b_m4 = (const float*)d_in[10];
    const float* W_i4 = (const float*)d_in[11];
    const float* g_i4 = (const float*)d_in[12];
    const float* b_i4 = (const float*)d_in[13];
    const float* W_m3 = (const float*)d_in[14];
    const float* g_m3 = (const float*)d_in[15];
    const float* b_m3 = (const float*)d_in[16];
    const float* W_i3 = (const float*)d_in[17];
    const float* g_i3 = (const float*)d_in[18];
    const float* b_i3 = (const float*)d_in[19];
    const float* W_m2 = (const float*)d_in[20];
    const float* g_m2 = (const float*)d_in[21];
    const float* b_m2 = (const float*)d_in[22];
    const float* W_i2 = (const float*)d_in[23];
    const float* g_i2 = (const float*)d_in[24];
    const float* b_i2 = (const float*)d_in[25];
    const float* W_m1 = (const float*)d_in[26];
    const float* g_m1 = (const float*)d_in[27];
    const float* b_m1 = (const float*)d_in[28];
    const float* W_c5 = (const float*)d_in[29];
    const float* g_c5 = (const float*)d_in[30];
    const float* b_c5 = (const float*)d_in[31];

    const int n4 = in_sizes[0] / 27;
    const int n3 = in_sizes[1] / 27;
    const int n2 = in_sizes[3] / 27;
    const int n1 = in_sizes[5] / 27;

    float *bufA, *bufB, *stats;
    int* perm;
    cudaGetSymbolAddress((void**)&bufA, g_bufA);
    cudaGetSymbolAddress((void**)&bufB, g_bufB);
    cudaGetSymbolAddress((void**)&stats, g_stats);
    cudaGetSymbolAddress((void**)&perm, g_perm);

    // dynamic smem: s_x = TN*(CI+4)*4; DENSE adds CI*CO*4 for s_w
    constexpr int SM_DENSE64 = (128 * 68 + 64 * 64) * 4;   // 51200
    constexpr int SM_CI64 = 128 * 68 * 4;                   // 34816
    constexpr int SM_CI32 = 128 * 36 * 4;                   // 18432
    constexpr int SM_CI16 = 128 * 20 * 4;                   // 10240

    cudaFuncSetAttribute(gemm3_kernel<64, 64, 256, 4, 2, false, true>,
                         cudaFuncAttributeMaxDynamicSharedMemorySize, SM_DENSE64);
    cudaFuncSetAttribute(gemm3_kernel<64, 64, 256, 4, 2, true, false>,
                         cudaFuncAttributeMaxDynamicSharedMemorySize, SM_CI64);
    cudaFuncSetAttribute(gemm3_kernel<64, 32, 128, 4, 4, true, false>,
                         cudaFuncAttributeMaxDynamicSharedMemorySize, SM_CI64);
    cudaFuncSetAttribute(gemm3_kernel<32, 32, 128, 4, 4, true, false>,
                         cudaFuncAttributeMaxDynamicSharedMemorySize, SM_CI32);
    cudaFuncSetAttribute(gemm3_kernel<32, 16, 128, 2, 4, true, false>,
                         cudaFuncAttributeMaxDynamicSharedMemorySize, SM_CI32);
    cudaFuncSetAttribute(gemm3_kernel<16, 16, 128, 2, 4, true, false>,
                         cudaFuncAttributeMaxDynamicSharedMemorySize, SM_CI16);

    // ---- perm build (L1 doesn't need it; runs before scatter) ----
    PermArgs pa;
    pa.tab[0] = nbr4;  pa.n[0] = n4;
    pa.tab[1] = inv43; pa.n[1] = n3;
    pa.tab[2] = nbr3;  pa.n[2] = n3;
    pa.tab[3] = inv32; pa.n[3] = n2;
    pa.tab[4] = nbr2;  pa.n[4] = n2;
    pa.tab[5] = inv21; pa.n[5] = n1;
    pa.tab[6] = nbr1;  pa.n[6] = n1;
    pa.cum[0] = 0;
    for (int l = 0; l < 7; ++l)
        pa.cum[l + 1] = pa.cum[l] + (pa.n[l] + 255) / 256;
    int nblk = pa.cum[7];

    zero_all_kernel<<<(7 * NB + 255) / 256, 256>>>();   // #0
    mask_hist_all_kernel<<<nblk, 256>>>(pa);             // #1
    scan_all_kernel<<<7, NB>>>();                        // #2

    // L1: m4 (x -> A), 64->64, N=n4, DENSE, identity perm.   launch #3
    gemm3_kernel<64, 64, 256, 4, 2, false, true><<<(n4 + 127) / 128, 256, SM_DENSE64>>>(
        x, nbr4, W_m4, nullptr, nullptr, nullptr, nullptr, 0,
        bufA, stats + 0 * 128, n4);

    scatter_all_kernel<<<nblk, 256>>>(pa);               // #4

    // L2: i4 (A -> B), 64->64, N=n3
    gemm3_kernel<64, 64, 256, 4, 2, true, false><<<(n3 + 127) / 128, 256, SM_CI64>>>(
        bufA, inv43, W_i4, perm + 1 * MAXROWS,
        stats + 0 * 128, g_m4, b_m4, n4, bufB, stats + 1 * 128, n3);

    // L3: m3 (B -> A), 64->64, N=n3
    gemm3_kernel<64, 64, 256, 4, 2, true, false><<<(n3 + 127) / 128, 256, SM_CI64>>>(
        bufB, nbr3, W_m3, perm + 2 * MAXROWS,
        stats + 1 * 128, g_i4, b_i4, n3, bufA, stats + 2 * 128, n3);

    // L4: i3 (A -> B), 64->32, N=n2
    gemm3_kernel<64, 32, 128, 4, 4, true, false><<<(n2 + 127) / 128, 128, SM_CI64>>>(
        bufA, inv32, W_i3, perm + 3 * MAXROWS,
        stats + 2 * 128, g_m3, b_m3, n3, bufB, stats + 3 * 128, n2);

    // L5: m2 (B -> A), 32->32, N=n2
    gemm3_kernel<32, 32, 128, 4, 4, true, false><<<(n2 + 127) / 128, 128, SM_CI32>>>(
        bufB, nbr2, W_m2, perm + 4 * MAXROWS,
        stats + 3 * 128, g_i3, b_i3, n2, bufA, stats + 4 * 128, n2);

    // L6: i2 (A -> B), 32->16, N=n1
    gemm3_kernel<32, 16, 128, 2, 4, true, false><<<(n1 + 127) / 128, 128, SM_CI32>>>(
        bufA, inv21, W_i2, perm + 5 * MAXROWS,
        stats + 4 * 128, g_m2, b_m2, n2, bufB, stats + 5 * 128, n1);

    // L7: m1 (B -> A), 16->16, N=n1
    gemm3_kernel<16, 16, 128, 2, 4, true, false><<<(n1 + 127) / 128, 128, SM_CI16>>>(
        bufB, nbr1, W_m1, perm + 6 * MAXROWS,
        stats + 5 * 128, g_i2, b_i2, n1, bufA, stats + 6 * 128, n1);

    // L8: c5 (A -> B raw), 16->3
    gemm_c5_kernel<<<(n1 + 255) / 256, 256>>>(
        bufA, nbr1, W_c5, perm + 6 * MAXROWS,
        stats + 6 * 128, g_m1, b_m1, n1, bufB, stats + 7 * 128, n1);

    // final normalize (no relu)
    out_kernel<<<256, 256>>>(bufB, stats + 7 * 128, g_c5, b_c5,
                             (float*)d_out, n1);
}

// round 14
// speedup vs baseline: 1.8222x; 1.0163x over previous
#include <cuda_runtime.h>
#include <math.h>

// ---------------------------------------------------------------------------
// VoxelBackBone8x decoder: 8 x (gather-GEMM over 27 taps + BN + relu)
// R14: == R12 (passed, 1264us) + ONE change: DENSE L1 weight staging is now
//      double-buffered (one __syncthreads per tap instead of two; staging of
//      W[k+1] overlaps gather/compute of tap k). Bisect step for the R13
//      correctness regression: sparse layers / gather are byte-identical R12.
// ---------------------------------------------------------------------------

#define MAXROWS 102400
#define NB 1024

__device__ float g_bufA[MAXROWS * 64];
__device__ float g_bufB[MAXROWS * 64];
__device__ float g_stats[8 * 2 * 64];   // per layer: [sum(64), sumsq(64)]
__device__ int      g_perm[7][MAXROWS];
__device__ unsigned g_keys[7][MAXROWS];
__device__ unsigned g_hist[7 * NB];
__device__ unsigned g_offs[7 * NB];
__device__ unsigned g_cnt[7 * NB];

struct PermArgs {
    const int* tab[7];
    int n[7];
    int cum[8];   // cumulative block counts (256-thread blocks)
};

// zeroes hist + cnt + stats in one launch
__global__ void zero_all_kernel() {
    int t = blockIdx.x * blockDim.x + threadIdx.x;
    if (t < 7 * NB) { g_hist[t] = 0u; g_cnt[t] = 0u; }
    if (t < 8 * 2 * 64) g_stats[t] = 0.f;
}

// ---------------------------------------------------------------------------
// Fused permutation build over all 7 layers.
// ---------------------------------------------------------------------------
__global__ void mask_hist_all_kernel(PermArgs pa) {
    __shared__ unsigned sh[NB];
    __shared__ int s_l;
    for (int i = threadIdx.x; i < NB; i += blockDim.x) sh[i] = 0;
    if (threadIdx.x == 0) {
        int l = 0;
        while (blockIdx.x >= (unsigned)pa.cum[l + 1]) ++l;
        s_l = l;
    }
    __syncthreads();
    int l = s_l;
    int i = (blockIdx.x - pa.cum[l]) * 256 + threadIdx.x;
    if (i < pa.n[l]) {
        const int* row = pa.tab[l] + (size_t)i * 27;
        unsigned m = 0;
#pragma unroll
        for (int k = 0; k < 27; ++k) m |= (row[k] >= 0 ? 1u : 0u) << k;
        unsigned key = (m * 2654435761u) >> 22;   // 10 bits
        g_keys[l][i] = key;
        atomicAdd(&sh[key], 1u);
    }
    __syncthreads();
    for (int j = threadIdx.x; j < NB; j += blockDim.x)
        if (sh[j]) atomicAdd(&g_hist[l * NB + j], sh[j]);
}

__global__ void scan_all_kernel() {   // grid = 7, block = NB
    __shared__ unsigned s[NB];
    int l = blockIdx.x;
    int t = threadIdx.x;
    unsigned h = g_hist[l * NB + t];
    s[t] = h;
    __syncthreads();
    for (int d = 1; d < NB; d <<= 1) {
        unsigned v = (t >= d) ? s[t - d] : 0;
        __syncthreads();
        s[t] += v;
        __syncthreads();
    }
    g_offs[l * NB + t] = s[t] - h;   // exclusive prefix
}

__global__ void scatter_all_kernel(PermArgs pa) {
    __shared__ unsigned bcnt[NB];
    __shared__ unsigned bbase[NB];
    __shared__ int s_l;
    for (int i = threadIdx.x; i < NB; i += blockDim.x) bcnt[i] = 0;
    if (threadIdx.x == 0) {
        int l = 0;
        while (blockIdx.x >= (unsigned)pa.cum[l + 1]) ++l;
        s_l = l;
    }
    __syncthreads();
    int l = s_l;
    int i = (blockIdx.x - pa.cum[l]) * 256 + threadIdx.x;
    unsigned key = 0, rank = 0;
    bool valid = (i < pa.n[l]);
    if (valid) { key = g_keys[l][i]; rank = atomicAdd(&bcnt[key], 1u); }
    __syncthreads();
    for (int j = threadIdx.x; j < NB; j += blockDim.x)
        if (bcnt[j]) bbase[j] = atomicAdd(&g_cnt[l * NB + j], bcnt[j]);
    __syncthreads();
    if (valid) g_perm[l][g_offs[l * NB + key] + bbase[key] + rank] = i;
}

// ---------------------------------------------------------------------------
// f32x2 helpers
// ---------------------------------------------------------------------------
__device__ __forceinline__ void ffma2(unsigned long long& d, unsigned long long a,
                                      unsigned long long b) {
    asm("fma.rn.f32x2 %0, %1, %2, %0;" : "+l"(d) : "l"(a), "l"(b));
}
__device__ __forceinline__ unsigned long long packf2(float x) {
    unsigned long long r;
    unsigned int u = __float_as_uint(x);
    asm("mov.b64 %0, {%1, %1};" : "=l"(r) : "r"(u));
    return r;
}
__device__ __forceinline__ float2 unpackf2(unsigned long long v) {
    float2 f;
    asm("mov.b64 {%0, %1}, %2;" : "=f"(f.x), "=f"(f.y) : "l"(v));
    return f;
}

// final layer: out[n,3] = y[n,3]*a + b (no relu), affine from stats
__global__ void out_kernel(const float* __restrict__ y, const float* __restrict__ stats,
                           const float* __restrict__ g, const float* __restrict__ b,
                           float* __restrict__ out, int N) {
    __shared__ float sa[3], sb[3];
    int c = threadIdx.x;
    if (c < 3) {
        float invN = 1.0f / (float)N;
        float mu = stats[c] * invN;
        float var = stats[64 + c] * invN - mu * mu;
        float a = g[c] * rsqrtf(var + 1e-3f);
        sa[c] = a;
        sb[c] = b[c] - mu * a;
    }
    __syncthreads();
    int total = N * 3;
    for (int i = blockIdx.x * blockDim.x + threadIdx.x; i < total;
         i += gridDim.x * blockDim.x) {
        int j = i % 3;
        out[i] = fmaf(y[i], sa[j], sb[j]);
    }
}

// ---------------------------------------------------------------------------
// gemm3: gather-GEMM over (optionally) mask-sorted rows.
//   NT threads; thread tile = RPT rows x 8 cols (split {4cg, H+4cg}).
//   Warp owns WR rows + its own s_x slice; iterates only its live taps.
//   DENSE: block-synchronous tap loop, DOUBLE-BUFFERED smem weights; one
//          __syncthreads per tap. Proof: compute(k) reads buf[k&1], staged
//          during iteration k-1 behind the sync; iteration k's prefetch
//          writes buf[(k+1)&1], whose last reader compute(k-1) drained at
//          the previous sync.
//  !DENSE: warp-private tap loop, weights straight from global (L1/L2).
//   APPLY: previous layer's BN affine computed IN-BLOCK from its stats.
//   perm == nullptr -> identity row order.
// ---------------------------------------------------------------------------
template <int CI, int CO, int NT, int RPT, int MB, bool APPLY, bool DENSE>
__launch_bounds__(NT, MB)
__global__ void gemm3_kernel(const float* __restrict__ in,
                             const int* __restrict__ nbr,
                             const float* __restrict__ W,    // [27][CI][CO]
                             const int* __restrict__ perm,   // [N] or null
                             const float* __restrict__ pstat,// prev stats
                             const float* __restrict__ pg,   // prev gamma
                             const float* __restrict__ pb,   // prev beta
                             int prevN,
                             float* __restrict__ out,        // [N][CO] raw
                             float* __restrict__ stats,      // [sum, sumsq]
                             int N) {
    constexpr int G = CO / 8;
    constexpr int ROWG = NT / G;
    constexpr int TN = ROWG * RPT;
    constexpr int CIP = CI + 4;
    constexpr int WR = (32 / G) * RPT;   // rows owned by one warp
    constexpr int C4 = CI / 4;
    constexpr int H = CO / 2;

    extern __shared__ float s_x[];       // TN*CIP (+ 2*CI*CO weights if DENSE)
    float* s_w = s_x + TN * CIP;

    __shared__ int s_rows[TN];
    __shared__ int s_nbr[TN * 27];
    __shared__ float s_stats[2][CO];
    __shared__ float s_a[CI], s_b[CI];

    const int tid = threadIdx.x;
    const int lane = tid & 31;
    const int warp = tid >> 5;
    const int rowbase = blockIdx.x * TN;

    if (tid < CO) { s_stats[0][tid] = 0.f; s_stats[1][tid] = 0.f; }
    if (APPLY) {
        for (int c = tid; c < CI; c += NT) {
            float invN = 1.0f / (float)prevN;
            float mu = pstat[c] * invN;
            float var = pstat[64 + c] * invN - mu * mu;
            float a = pg[c] * rsqrtf(var + 1e-3f);
            s_a[c] = a;
            s_b[c] = pb[c] - mu * a;
        }
    }
    for (int i = tid; i < TN; i += NT) {
        int gr = rowbase + i;
        s_rows[i] = (gr < N) ? (perm ? perm[gr] : gr) : -1;
    }
    __syncthreads();
    // stage neighbor rows for the tile
    for (int i = tid; i < TN * 27; i += NT) {
        int r = i / 27;
        int k = i - r * 27;
        int row = s_rows[r];
        s_nbr[i] = (row >= 0) ? nbr[(size_t)row * 27 + k] : -1;
    }
    __syncthreads();

    const int cg = tid % G;
    const int rg = tid / G;
    const int r0 = rg * RPT;
    const int wbase = warp * WR;         // first row owned by this warp

    // warp-live tap mask (union over this warp's WR rows)
    unsigned m = 0;
    for (int i = lane; i < WR * 27; i += 32) {
        int r = wbase + i / 27;
        int k = i - (i / 27) * 27;
        if (s_nbr[r * 27 + k] >= 0) m |= 1u << k;
    }
    m = __reduce_or_sync(0xffffffffu, m);

    unsigned long long acc[RPT][4];
#pragma unroll
    for (int i = 0; i < RPT; ++i)
#pragma unroll
        for (int j = 0; j < 4; ++j) acc[i][j] = 0ULL;

    // warp-private gather of WR rows for tap k (applies prev BN+relu)
    auto gather = [&](int k) {
        for (int i = lane; i < WR * C4; i += 32) {
            int rl = i / C4;
            int c4 = i - rl * C4;
            int r = wbase + rl;
            int idx = s_nbr[r * 27 + k];
            float4 val = make_float4(0.f, 0.f, 0.f, 0.f);
            if (idx >= 0) {
                val = *(const float4*)(in + (size_t)idx * CI + c4 * 4);
                if (APPLY) {
                    int c = c4 * 4;
                    val.x = fmaxf(fmaf(val.x, s_a[c + 0], s_b[c + 0]), 0.f);
                    val.y = fmaxf(fmaf(val.y, s_a[c + 1], s_b[c + 1]), 0.f);
                    val.z = fmaxf(fmaf(val.z, s_a[c + 2], s_b[c + 2]), 0.f);
                    val.w = fmaxf(fmaf(val.w, s_a[c + 3], s_b[c + 3]), 0.f);
                }
            }
            *(float4*)(s_x + r * CIP + c4 * 4) = val;
        }
    };

    // FFMA2 block over one tap, weights via 16B vectors at base Wk
    auto compute = [&](const ulonglong2* __restrict__ Wk) {
#pragma unroll 2
        for (int c = 0; c < CI; c += 2) {
            ulonglong2 wa0 = Wk[(c * CO + 4 * cg) >> 2];
            ulonglong2 wa1 = Wk[(c * CO + H + 4 * cg) >> 2];
            ulonglong2 wb0 = Wk[((c + 1) * CO + 4 * cg) >> 2];
            ulonglong2 wb1 = Wk[((c + 1) * CO + H + 4 * cg) >> 2];
#pragma unroll
            for (int i = 0; i < RPT; ++i) {
                float2 xv = *(const float2*)(s_x + (r0 + i) * CIP + c);
                unsigned long long xa = packf2(xv.x);
                unsigned long long xb = packf2(xv.y);
                ffma2(acc[i][0], xa, wa0.x);
                ffma2(acc[i][1], xa, wa0.y);
                ffma2(acc[i][2], xa, wa1.x);
                ffma2(acc[i][3], xa, wa1.y);
                ffma2(acc[i][0], xb, wb0.x);
                ffma2(acc[i][1], xb, wb0.y);
                ffma2(acc[i][2], xb, wb1.x);
                ffma2(acc[i][3], xb, wb1.y);
            }
        }
    };

    if (DENSE) {
        // stage tap 0 into buffer 0
        {
            const float4* Wk4 = (const float4*)W;
            for (int v = tid; v < CI * CO / 4; v += NT)
                ((float4*)s_w)[v] = Wk4[v];
        }
        __syncthreads();
        for (int k = 0; k < 27; ++k) {
            // prefetch next tap's weights into the other buffer
            if (k + 1 < 27) {
                const float4* Wn = (const float4*)(W + (size_t)(k + 1) * CI * CO);
                float4* dst = (float4*)(s_w + ((k + 1) & 1) * (CI * CO));
                for (int v = tid; v < CI * CO / 4; v += NT) dst[v] = Wn[v];
            }
            if ((m >> k) & 1u) {
                gather(k);
                __syncwarp();   // s_x rows are warp-private
                compute((const ulonglong2*)(s_w + (k & 1) * (CI * CO)));
            }
            __syncthreads();   // compute(k) + stage(k+1) complete
        }
    } else {
        // warp-private loop, weights straight from global (L1/L2 cached)
        unsigned mm = m;
        while (mm) {
            const int k = __ffs(mm) - 1;
            mm &= mm - 1;
            gather(k);
            __syncwarp();
            compute((const ulonglong2*)(W + (size_t)k * CI * CO));
            __syncwarp();   // all lanes done reading s_x before next gather
        }
    }

    // epilogue: store raw y + accumulate stats
#pragma unroll
    for (int j = 0; j < 4; ++j) {
        float s1 = 0.f, s2 = 0.f, t1 = 0.f, t2 = 0.f;
#pragma unroll
        for (int i = 0; i < RPT; ++i) {
            if (s_rows[r0 + i] >= 0) {
                float2 p = unpackf2(acc[i][j]);
                s1 += p.x; s2 += p.x * p.x;
                t1 += p.y; t2 += p.y * p.y;
            }
        }
        int base = (j < 2) ? (4 * cg + 2 * j) : (H + 4 * cg + 2 * (j - 2));
        atomicAdd(&s_stats[0][base + 0], s1);
        atomicAdd(&s_stats[1][base + 0], s2);
        atomicAdd(&s_stats[0][base + 1], t1);
        atomicAdd(&s_stats[1][base + 1], t2);
    }
#pragma unroll
    for (int i = 0; i < RPT; ++i) {
        int row = s_rows[r0 + i];
        if (row >= 0) {
            float2 p0 = unpackf2(acc[i][0]);
            float2 p1 = unpackf2(acc[i][1]);
            float2 p2 = unpackf2(acc[i][2]);
            float2 p3 = unpackf2(acc[i][3]);
            *(float4*)(out + (size_t)row * CO + 4 * cg) =
                make_float4(p0.x, p0.y, p1.x, p1.y);
            *(float4*)(out + (size_t)row * CO + H + 4 * cg) =
                make_float4(p2.x, p2.y, p3.x, p3.y);
        }
    }
    __syncthreads();
    if (tid < CO) {
        atomicAdd(&stats[tid], s_stats[0][tid]);
        atomicAdd(&stats[64 + tid], s_stats[1][tid]);
    }
}

// ---------------------------------------------------------------------------
// Final 16->3 conv: one row per lane, register-resident, warp-private tap
// loop; prev-layer affine computed in-block from stats.
// ---------------------------------------------------------------------------
__launch_bounds__(256, 4)
__global__ void gemm_c5_kernel(const float* __restrict__ in,
                               const int* __restrict__ nbr,
                               const float* __restrict__ W,     // [27][16][3]
                               const int* __restrict__ perm,
                               const float* __restrict__ pstat, // layer-7 stats
                               const float* __restrict__ pg,
                               const float* __restrict__ pb,
                               int prevN,
                               float* __restrict__ out,         // [N][3] raw
                               float* __restrict__ stats,
                               int N) {
    constexpr int CI = 16, TN = 256;

    __shared__ int s_rows[TN];
    __shared__ int s_nbr[TN * 27];
    __shared__ float s_a[CI], s_b[CI];
    __shared__ float s_stats[2][4];

    const int tid = threadIdx.x;
    const int rowbase = blockIdx.x * TN;

    if (tid < 4) { s_stats[0][tid] = 0.f; s_stats[1][tid] = 0.f; }
    if (tid < CI) {
        float invN = 1.0f / (float)prevN;
        float mu = pstat[tid] * invN;
        float var = pstat[64 + tid] * invN - mu * mu;
        float a = pg[tid] * rsqrtf(var + 1e-3f);
        s_a[tid] = a;
        s_b[tid] = pb[tid] - mu * a;
    }
    {
        int gr = rowbase + tid;
        s_rows[tid] = (gr < N) ? perm[gr] : -1;
    }
    __syncthreads();
    for (int i = tid; i < TN * 27; i += 256) {
        int r = i / 27;
        int row = s_rows[r];
        s_nbr[i] = (row >= 0) ? nbr[(size_t)row * 27 + (i - r * 27)] : -1;
    }
    __syncthreads();

    unsigned m = 0;
#pragma unroll
    for (int k = 0; k < 27; ++k)
        if (s_nbr[tid * 27 + k] >= 0) m |= 1u << k;
    unsigned wm = __reduce_or_sync(0xffffffffu, m);

    float acc[3] = {0.f, 0.f, 0.f};

    while (wm) {
        const int k = __ffs(wm) - 1;
        wm &= wm - 1;
        int idx = s_nbr[tid * 27 + k];
        if (idx >= 0) {
            const float* xr = in + (size_t)idx * CI;
            const float* wk = W + (size_t)k * CI * 3;
#pragma unroll
            for (int c4 = 0; c4 < 4; ++c4) {
                float4 v = *(const float4*)(xr + c4 * 4);
                int c = c4 * 4;
                v.x = fmaxf(fmaf(v.x, s_a[c + 0], s_b[c + 0]), 0.f);
                v.y = fmaxf(fmaf(v.y, s_a[c + 1], s_b[c + 1]), 0.f);
                v.z = fmaxf(fmaf(v.z, s_a[c + 2], s_b[c + 2]), 0.f);
                v.w = fmaxf(fmaf(v.w, s_a[c + 3], s_b[c + 3]), 0.f);
                float xs[4] = {v.x, v.y, v.z, v.w};
#pragma unroll
                for (int u = 0; u < 4; ++u) {
                    acc[0] = fmaf(xs[u], __ldg(wk + (c + u) * 3 + 0), acc[0]);
                    acc[1] = fmaf(xs[u], __ldg(wk + (c + u) * 3 + 1), acc[1]);
                    acc[2] = fmaf(xs[u], __ldg(wk + (c + u) * 3 + 2), acc[2]);
                }
            }
        }
    }

    int row = s_rows[tid];
#pragma unroll
    for (int j = 0; j < 3; ++j) {
        float y = (row >= 0) ? acc[j] : 0.f;
        atomicAdd(&s_stats[0][j], y);
        atomicAdd(&s_stats[1][j], y * y);
    }
    if (row >= 0) {
#pragma unroll
        for (int j = 0; j < 3; ++j) out[(size_t)row * 3 + j] = acc[j];
    }
    __syncthreads();
    if (tid < 3) {
        atomicAdd(&stats[tid], s_stats[0][tid]);
        atomicAdd(&stats[64 + tid], s_stats[1][tid]);
    }
}

extern "C" void kernel_launch(void* const* d_in, const int* in_sizes, int n_in,
                              void* d_out, int out_size) {
    const int* nbr4  = (const int*)d_in[0];
    const int* inv43 = (const int*)d_in[1];
    const int* nbr3  = (const int*)d_in[2];
    const int* inv32 = (const int*)d_in[3];
    const int* nbr2  = (const int*)d_in[4];
    const int* inv21 = (const int*)d_in[5];
    const int* nbr1  = (const int*)d_in[6];
    const float* x   = (const float*)d_in[7];

    const float* W_m4 = (const float*)d_in[8];
    const float* g_m4 = (const float*)d_in[9];
    const float* b_m4 = (const float*)d_in[10];
    const float* W_i4 = (const float*)d_in[11];
    const float* g_i4 = (const float*)d_in[12];
    const float* b_i4 = (const float*)d_in[13];
    const float* W_m3 = (const float*)d_in[14];
    const float* g_m3 = (const float*)d_in[15];
    const float* b_m3 = (const float*)d_in[16];
    const float* W_i3 = (const float*)d_in[17];
    const float* g_i3 = (const float*)d_in[18];
    const float* b_i3 = (const float*)d_in[19];
    const float* W_m2 = (const float*)d_in[20];
    const float* g_m2 = (const float*)d_in[21];
    const float* b_m2 = (const float*)d_in[22];
    const float* W_i2 = (const float*)d_in[23];
    const float* g_i2 = (const float*)d_in[24];
    const float* b_i2 = (const float*)d_in[25];
    const float* W_m1 = (const float*)d_in[26];
    const float* g_m1 = (const float*)d_in[27];
    const float* b_m1 = (const float*)d_in[28];
    const float* W_c5 = (const float*)d_in[29];
    const float* g_c5 = (const float*)d_in[30];
    const float* b_c5 = (const float*)d_in[31];

    const int n4 = in_sizes[0] / 27;
    const int n3 = in_sizes[1] / 27;
    const int n2 = in_sizes[3] / 27;
    const int n1 = in_sizes[5] / 27;

    float *bufA, *bufB, *stats;
    int* perm;
    cudaGetSymbolAddress((void**)&bufA, g_bufA);
    cudaGetSymbolAddress((void**)&bufB, g_bufB);
    cudaGetSymbolAddress((void**)&stats, g_stats);
    cudaGetSymbolAddress((void**)&perm, g_perm);

    // dynamic smem: s_x = TN*(CI+4)*4; DENSE adds 2*CI*CO*4 for s_w
    constexpr int SM_DENSE64 = (128 * 68 + 2 * 64 * 64) * 4;  // 67584
    constexpr int SM_CI64 = 128 * 68 * 4;                      // 34816
    constexpr int SM_CI32 = 128 * 36 * 4;                      // 18432
    constexpr int SM_CI16 = 128 * 20 * 4;                      // 10240

    cudaFuncSetAttribute(gemm3_kernel<64, 64, 256, 4, 2, false, true>,
                         cudaFuncAttributeMaxDynamicSharedMemorySize, SM_DENSE64);
    cudaFuncSetAttribute(gemm3_kernel<64, 64, 256, 4, 2, true, false>,
                         cudaFuncAttributeMaxDynamicSharedMemorySize, SM_CI64);
    cudaFuncSetAttribute(gemm3_kernel<64, 32, 128, 4, 4, true, false>,
                         cudaFuncAttributeMaxDynamicSharedMemorySize, SM_CI64);
    cudaFuncSetAttribute(gemm3_kernel<32, 32, 128, 4, 4, true, false>,
                         cudaFuncAttributeMaxDynamicSharedMemorySize, SM_CI32);
    cudaFuncSetAttribute(gemm3_kernel<32, 16, 128, 2, 4, true, false>,
                         cudaFuncAttributeMaxDynamicSharedMemorySize, SM_CI32);
    cudaFuncSetAttribute(gemm3_kernel<16, 16, 128, 2, 4, true, false>,
                         cudaFuncAttributeMaxDynamicSharedMemorySize, SM_CI16);

    // ---- perm build (L1 doesn't need it; runs before scatter) ----
    PermArgs pa;
    pa.tab[0] = nbr4;  pa.n[0] = n4;
    pa.tab[1] = inv43; pa.n[1] = n3;
    pa.tab[2] = nbr3;  pa.n[2] = n3;
    pa.tab[3] = inv32; pa.n[3] = n2;
    pa.tab[4] = nbr2;  pa.n[4] = n2;
    pa.tab[5] = inv21; pa.n[5] = n1;
    pa.tab[6] = nbr1;  pa.n[6] = n1;
    pa.cum[0] = 0;
    for (int l = 0; l < 7; ++l)
        pa.cum[l + 1] = pa.cum[l] + (pa.n[l] + 255) / 256;
    int nblk = pa.cum[7];

    zero_all_kernel<<<(7 * NB + 255) / 256, 256>>>();   // #0
    mask_hist_all_kernel<<<nblk, 256>>>(pa);             // #1
    scan_all_kernel<<<7, NB>>>();                        // #2

    // L1: m4 (x -> A), 64->64, N=n4, DENSE, identity perm.   launch #3
    gemm3_kernel<64, 64, 256, 4, 2, false, true><<<(n4 + 127) / 128, 256, SM_DENSE64>>>(
        x, nbr4, W_m4, nullptr, nullptr, nullptr, nullptr, 0,
        bufA, stats + 0 * 128, n4);

    scatter_all_kernel<<<nblk, 256>>>(pa);               // #4

    // L2: i4 (A -> B), 64->64, N=n3
    gemm3_kernel<64, 64, 256, 4, 2, true, false><<<(n3 + 127) / 128, 256, SM_CI64>>>(
        bufA, inv43, W_i4, perm + 1 * MAXROWS,
        stats + 0 * 128, g_m4, b_m4, n4, bufB, stats + 1 * 128, n3);

    // L3: m3 (B -> A), 64->64, N=n3
    gemm3_kernel<64, 64, 256, 4, 2, true, false><<<(n3 + 127) / 128, 256, SM_CI64>>>(
        bufB, nbr3, W_m3, perm + 2 * MAXROWS,
        stats + 1 * 128, g_i4, b_i4, n3, bufA, stats + 2 * 128, n3);

    // L4: i3 (A -> B), 64->32, N=n2
    gemm3_kernel<64, 32, 128, 4, 4, true, false><<<(n2 + 127) / 128, 128, SM_CI64>>>(
        bufA, inv32, W_i3, perm + 3 * MAXROWS,
        stats + 2 * 128, g_m3, b_m3, n3, bufB, stats + 3 * 128, n2);

    // L5: m2 (B -> A), 32->32, N=n2
    gemm3_kernel<32, 32, 128, 4, 4, true, false><<<(n2 + 127) / 128, 128, SM_CI32>>>(
        bufB, nbr2, W_m2, perm + 4 * MAXROWS,
        stats + 3 * 128, g_i3, b_i3, n2, bufA, stats + 4 * 128, n2);

    // L6: i2 (A -> B), 32->16, N=n1
    gemm3_kernel<32, 16, 128, 2, 4, true, false><<<(n1 + 127) / 128, 128, SM_CI32>>>(
        bufA, inv21, W_i2, perm + 5 * MAXROWS,
        stats + 4 * 128, g_m2, b_m2, n2, bufB, stats + 5 * 128, n1);

    // L7: m1 (B -> A), 16->16, N=n1
    gemm3_kernel<16, 16, 128, 2, 4, true, false><<<(n1 + 127) / 128, 128, SM_CI16>>>(
        bufB, nbr1, W_m1, perm + 6 * MAXROWS,
        stats + 5 * 128, g_i2, b_i2, n1, bufA, stats + 6 * 128, n1);

    // L8: c5 (A -> B raw), 16->3
    gemm_c5_kernel<<<(n1 + 255) / 256, 256>>>(
        bufA, nbr1, W_c5, perm + 6 * MAXROWS,
        stats + 6 * 128, g_m1, b_m1, n1, bufB, stats + 7 * 128, n1);

    // final normalize (no relu)
    out_kernel<<<256, 256>>>(bufB, stats + 7 * 128, g_c5, b_c5,
                             (float*)d_out, n1);
}